// round 2
// baseline (speedup 1.0000x reference)
#include <cuda_runtime.h>

// Problem constants
#define BB   8
#define SS   4096
#define DD   256
#define NW   8
#define WINS 512
#define HH   2
#define KD   256
#define DFF  1024
#define MTOK (BB*SS)          // 32768 tokens

// ---------------- device scratch (static allocation; no cudaMalloc) -------
__device__ float g_q  [(size_t)BB*SS*HH*KD];   // [b,w,h,s,k]  64MB
__device__ float g_k  [(size_t)BB*SS*HH*KD];
__device__ float g_v  [(size_t)BB*SS*HH*KD];
__device__ float g_ctx[(size_t)BB*SS*HH*KD];   // [token, h*K+k]
__device__ float g_y  [(size_t)MTOK*DD];       // post-LN1
__device__ float g_t  [(size_t)MTOK*DD];       // pre-LN scratch
__device__ float g_h  [(size_t)MTOK*DFF];      // FFN hidden

// ---------------- generic tiled fp32 GEMM ---------------------------------
// C[M,N] = A[M,Kd] @ B[Kd,N] + bias[N]; EPI: 0 plain, 1 relu, 2 qkv-scatter
template<int EPI>
__global__ __launch_bounds__(256)
void gemm_k(const float* __restrict__ A, const float* __restrict__ Bm,
            const float* __restrict__ bias, float* __restrict__ C,
            int M, int N, int Kd)
{
    __shared__ float As[16][64];     // [k][m]
    __shared__ float Bs[16][132];    // [k][n] (+pad)

    const int m0 = blockIdx.y * 64;
    const int n0 = blockIdx.x * 128;
    const int tid = threadIdx.x;
    const int tm = tid >> 4, tn = tid & 15;

    float acc[4][8];
#pragma unroll
    for (int i = 0; i < 4; i++)
#pragma unroll
        for (int j = 0; j < 8; j++) acc[i][j] = 0.f;

    const int am  = tid >> 2;
    const int ak4 = (tid & 3) * 4;

    for (int k0 = 0; k0 < Kd; k0 += 16) {
        // A tile 64x16 (transposed into smem)
        float4 av = *(const float4*)&A[(size_t)(m0 + am) * Kd + k0 + ak4];
        As[ak4 + 0][am] = av.x;
        As[ak4 + 1][am] = av.y;
        As[ak4 + 2][am] = av.z;
        As[ak4 + 3][am] = av.w;
        // B tile 16x128
#pragma unroll
        for (int i = 0; i < 2; i++) {
            int lin = tid + i * 256;
            int r = lin >> 5, c = (lin & 31) * 4;
            float4 bv = *(const float4*)&Bm[(size_t)(k0 + r) * N + n0 + c];
            *(float4*)&Bs[r][c] = bv;
        }
        __syncthreads();
#pragma unroll
        for (int kk = 0; kk < 16; kk++) {
            float a[4], b[8];
#pragma unroll
            for (int i = 0; i < 4; i++) a[i] = As[kk][tm * 4 + i];
#pragma unroll
            for (int j = 0; j < 8; j++) b[j] = Bs[kk][tn * 8 + j];
#pragma unroll
            for (int i = 0; i < 4; i++)
#pragma unroll
                for (int j = 0; j < 8; j++) acc[i][j] += a[i] * b[j];
        }
        __syncthreads();
    }

#pragma unroll
    for (int i = 0; i < 4; i++) {
        int row = m0 + tm * 4 + i;
#pragma unroll
        for (int j = 0; j < 8; j++) {
            int col = n0 + tn * 8 + j;
            float cv = acc[i][j] + bias[col];
            if (EPI == 1) cv = fmaxf(cv, 0.f);
            if (EPI == 2) {
                // row = b*S + sg ; col = h*K + kd  ->  [b,w,h,sl,kd]
                int b_ = row >> 12, sg = row & 4095;
                int w  = sg >> 9,   sl = sg & 511;
                int h  = col >> 8,  kd = col & 255;
                size_t idx = (((size_t)((b_ * NW + w) * HH + h)) * WINS + sl) * KD + kd;
                C[idx] = cv;
            } else {
                C[(size_t)row * N + col] = cv;
            }
        }
    }
}

// ---------------- windowed attention --------------------------------------
// grid: (WIN/64 = 8, B*NW*H = 128), 256 threads
// smem: sS[64][513] scores, sQ[256][65] q^T, sT[16][68] streaming tile
#define SMEM_ATTN ((64*513 + 256*65 + 16*68) * 4)

__global__ __launch_bounds__(256)
void attn_k(const float* __restrict__ q, const float* __restrict__ k,
            const float* __restrict__ v, float* __restrict__ ctx)
{
    extern __shared__ float sm[];
    float* sS = sm;                    // 64 x 513
    float* sQ = sm + 64 * 513;         // 256 x 65 (kd-major)
    float* sT = sQ + 256 * 65;         // 16 x 68

    const int bwh = blockIdx.y;
    const int m0  = blockIdx.x * 64;
    const size_t base = (size_t)bwh * WINS * KD;
    const int tid = threadIdx.x;
    const int tm = tid >> 4, tn = tid & 15;

    // load Q tile [64 x 256] transposed into sQ[kd][m]
    for (int idx = tid; idx < 64 * 64; idx += 256) {
        int m = idx >> 6, c4 = (idx & 63) * 4;
        float4 f = *(const float4*)&q[base + (size_t)(m0 + m) * KD + c4];
        sQ[(c4 + 0) * 65 + m] = f.x;
        sQ[(c4 + 1) * 65 + m] = f.y;
        sQ[(c4 + 2) * 65 + m] = f.z;
        sQ[(c4 + 3) * 65 + m] = f.w;
    }
    __syncthreads();

    // ---- phase 1: scores = Q K^T / 16 ----
    for (int nt = 0; nt < 8; nt++) {
        int n0 = nt * 64;
        float acc[4][4];
#pragma unroll
        for (int i = 0; i < 4; i++)
#pragma unroll
            for (int j = 0; j < 4; j++) acc[i][j] = 0.f;

        for (int kc = 0; kc < 16; kc++) {
            // K tile: 64 keys x 16 dims, transposed -> sT[kk][n]
            {
                int n = tid >> 2, k4 = (tid & 3) * 4;
                float4 f = *(const float4*)&k[base + (size_t)(n0 + n) * KD + kc * 16 + k4];
                sT[(k4 + 0) * 68 + n] = f.x;
                sT[(k4 + 1) * 68 + n] = f.y;
                sT[(k4 + 2) * 68 + n] = f.z;
                sT[(k4 + 3) * 68 + n] = f.w;
            }
            __syncthreads();
#pragma unroll
            for (int kk = 0; kk < 16; kk++) {
                float a[4], b[4];
#pragma unroll
                for (int i = 0; i < 4; i++) a[i] = sQ[(kc * 16 + kk) * 65 + tm * 4 + i];
#pragma unroll
                for (int j = 0; j < 4; j++) b[j] = sT[kk * 68 + tn * 4 + j];
#pragma unroll
                for (int i = 0; i < 4; i++)
#pragma unroll
                    for (int j = 0; j < 4; j++) acc[i][j] += a[i] * b[j];
            }
            __syncthreads();
        }
#pragma unroll
        for (int i = 0; i < 4; i++)
#pragma unroll
            for (int j = 0; j < 4; j++)
                sS[(tm * 4 + i) * 513 + n0 + tn * 4 + j] = acc[i][j] * 0.0625f;
    }
    __syncthreads();

    // ---- softmax: 8 warps x 8 rows ----
    {
        int wid = tid >> 5, lane = tid & 31;
        for (int rr = 0; rr < 8; rr++) {
            int r = wid * 8 + rr;
            float mx = -1e30f;
            for (int c = lane; c < 512; c += 32) mx = fmaxf(mx, sS[r * 513 + c]);
#pragma unroll
            for (int o = 16; o; o >>= 1) mx = fmaxf(mx, __shfl_xor_sync(0xffffffffu, mx, o));
            float sum = 0.f;
            for (int c = lane; c < 512; c += 32) {
                float e = expf(sS[r * 513 + c] - mx);
                sS[r * 513 + c] = e;
                sum += e;
            }
#pragma unroll
            for (int o = 16; o; o >>= 1) sum += __shfl_xor_sync(0xffffffffu, sum, o);
            float inv = 1.f / sum;
            for (int c = lane; c < 512; c += 32) sS[r * 513 + c] *= inv;
        }
    }
    __syncthreads();

    // ---- phase 2: ctx = attn @ V ----
    const int b_ = bwh >> 4, w = (bwh >> 1) & 7, h = bwh & 1;
    for (int nt = 0; nt < 4; nt++) {
        int n0 = nt * 64;
        float acc[4][4];
#pragma unroll
        for (int i = 0; i < 4; i++)
#pragma unroll
            for (int j = 0; j < 4; j++) acc[i][j] = 0.f;

        for (int kc = 0; kc < 32; kc++) {
            __syncthreads();
            {
                int r = tid >> 4, c4 = (tid & 15) * 4;
                float4 f = *(const float4*)&v[base + (size_t)(kc * 16 + r) * KD + n0 + c4];
                *(float4*)&sT[r * 68 + c4] = f;
            }
            __syncthreads();
#pragma unroll
            for (int kk = 0; kk < 16; kk++) {
                float a[4], b[4];
#pragma unroll
                for (int i = 0; i < 4; i++) a[i] = sS[(tm * 4 + i) * 513 + kc * 16 + kk];
#pragma unroll
                for (int j = 0; j < 4; j++) b[j] = sT[kk * 68 + tn * 4 + j];
#pragma unroll
                for (int i = 0; i < 4; i++)
#pragma unroll
                    for (int j = 0; j < 4; j++) acc[i][j] += a[i] * b[j];
            }
        }
#pragma unroll
        for (int i = 0; i < 4; i++) {
            int token = b_ * SS + w * WINS + m0 + tm * 4 + i;
#pragma unroll
            for (int j = 0; j < 4; j++) {
                int col = h * KD + n0 + tn * 4 + j;
                ctx[(size_t)token * (HH * KD) + col] = acc[i][j];
            }
        }
    }
}

// ---------------- residual + LayerNorm -------------------------------------
// out[row] = LN(a[row] + r[row]) * g + b ; rows of width 256; 1 warp per row
__global__ __launch_bounds__(256)
void ln_k(const float* __restrict__ a, const float* __restrict__ r,
          const float* __restrict__ g, const float* __restrict__ bta,
          float* __restrict__ out)
{
    int wid = threadIdx.x >> 5, lane = threadIdx.x & 31;
    size_t row = (size_t)blockIdx.x * 8 + wid;
    const float* pa = a + row * DD;
    const float* pr = r + row * DD;
    float v[8];
    float s = 0.f;
#pragma unroll
    for (int j = 0; j < 8; j++) {
        int c = lane + j * 32;
        v[j] = pa[c] + pr[c];
        s += v[j];
    }
#pragma unroll
    for (int o = 16; o; o >>= 1) s += __shfl_xor_sync(0xffffffffu, s, o);
    float mu = s * (1.f / 256.f);
    float vs = 0.f;
#pragma unroll
    for (int j = 0; j < 8; j++) {
        float d = v[j] - mu;
        vs += d * d;
    }
#pragma unroll
    for (int o = 16; o; o >>= 1) vs += __shfl_xor_sync(0xffffffffu, vs, o);
    float inv = rsqrtf(vs * (1.f / 256.f) + 1e-3f);
#pragma unroll
    for (int j = 0; j < 8; j++) {
        int c = lane + j * 32;
        out[row * DD + c] = (v[j] - mu) * inv * g[c] + bta[c];
    }
}

// ---------------- launch ----------------------------------------------------
extern "C" void kernel_launch(void* const* d_in, const int* in_sizes, int n_in,
                              void* d_out, int out_size)
{
    const float* x    = (const float*)d_in[0];
    const float* Wq   = (const float*)d_in[1];
    const float* bq   = (const float*)d_in[2];
    const float* Wk   = (const float*)d_in[3];
    const float* bk   = (const float*)d_in[4];
    const float* Wv   = (const float*)d_in[5];
    const float* bv   = (const float*)d_in[6];
    const float* Wo   = (const float*)d_in[7];
    const float* bo   = (const float*)d_in[8];
    const float* ln1g = (const float*)d_in[9];
    const float* ln1b = (const float*)d_in[10];
    const float* W1   = (const float*)d_in[11];
    const float* b1   = (const float*)d_in[12];
    const float* W2   = (const float*)d_in[13];
    const float* b2   = (const float*)d_in[14];
    const float* ln2g = (const float*)d_in[15];
    const float* ln2b = (const float*)d_in[16];

    float *q, *k, *v, *ctx, *y, *t, *hbuf;
    cudaGetSymbolAddress((void**)&q,    g_q);
    cudaGetSymbolAddress((void**)&k,    g_k);
    cudaGetSymbolAddress((void**)&v,    g_v);
    cudaGetSymbolAddress((void**)&ctx,  g_ctx);
    cudaGetSymbolAddress((void**)&y,    g_y);
    cudaGetSymbolAddress((void**)&t,    g_t);
    cudaGetSymbolAddress((void**)&hbuf, g_h);

    cudaFuncSetAttribute(attn_k, cudaFuncAttributeMaxDynamicSharedMemorySize, SMEM_ATTN);

    dim3 blk(256);

    // QKV projections (scatter into [b,w,h,s,k])
    gemm_k<2><<<dim3(4, 512), blk>>>(x, Wq, bq, q, MTOK, HH * KD, DD);
    gemm_k<2><<<dim3(4, 512), blk>>>(x, Wk, bk, k, MTOK, HH * KD, DD);
    gemm_k<2><<<dim3(4, 512), blk>>>(x, Wv, bv, v, MTOK, HH * KD, DD);

    // windowed attention
    attn_k<<<dim3(8, 128), blk, SMEM_ATTN>>>(q, k, v, ctx);

    // output projection + LN1
    gemm_k<0><<<dim3(2, 512), blk>>>(ctx, Wo, bo, t, MTOK, DD, HH * KD);
    ln_k<<<MTOK / 8, blk>>>(t, x, ln1g, ln1b, y);

    // FFN
    gemm_k<1><<<dim3(8, 512), blk>>>(y, W1, b1, hbuf, MTOK, DFF, DD);
    gemm_k<0><<<dim3(2, 512), blk>>>(hbuf, W2, b2, t, MTOK, DD, DFF);
    ln_k<<<MTOK / 8, blk>>>(t, y, ln2g, ln2b, (float*)d_out);
}

// round 3
// speedup vs baseline: 1.8833x; 1.8833x over previous
#include <cuda_runtime.h>
#include <mma.h>
using namespace nvcuda;

// Problem constants
#define BB   8
#define SS   4096
#define DD   256
#define NW   8
#define WINS 512
#define HH   2
#define KD   256
#define DFF  1024
#define MTOK (BB*SS)          // 32768 tokens

// ---------------- device scratch (static allocation; no cudaMalloc) -------
__device__ float g_q  [(size_t)BB*SS*HH*KD];   // [b,w,h,s,k]
__device__ float g_k  [(size_t)BB*SS*HH*KD];
__device__ float g_v  [(size_t)BB*SS*HH*KD];
__device__ float g_ctx[(size_t)BB*SS*HH*KD];   // [token, h*K+k]
__device__ float g_y  [(size_t)MTOK*DD];       // post-LN1
__device__ float g_t  [(size_t)MTOK*DD];       // pre-LN scratch
__device__ float g_h  [(size_t)MTOK*DFF];      // FFN hidden

// ---------------- tf32 tensor-core GEMM ------------------------------------
// C[M,N] = A[M,Kd] @ B[Kd,N] + bias[N]; EPI: 0 plain, 1 relu, 2 qkv-scatter
// block tile 128x128, k-chunk 32, 8 warps (2x4), warp tile 64x32
#define GEMM_SMEM (128*132*4)

template<int EPI>
__global__ __launch_bounds__(256)
void gemm_tc(const float* __restrict__ A, const float* __restrict__ Bm,
             const float* __restrict__ bias, float* __restrict__ C,
             int M, int N, int Kd)
{
    extern __shared__ float sm[];
    float* As = sm;              // [128][36]
    float* Bs = sm + 128 * 36;   // [32][132]

    const int m0 = blockIdx.y * 128;
    const int n0 = blockIdx.x * 128;
    const int tid = threadIdx.x;
    const int wid = tid >> 5;
    const int wr = wid >> 2;     // 0..1  -> 64 rows
    const int wc = wid & 3;      // 0..3  -> 32 cols

    wmma::fragment<wmma::accumulator, 16, 16, 8, float> acc[4][2];
#pragma unroll
    for (int i = 0; i < 4; i++)
#pragma unroll
        for (int j = 0; j < 2; j++) wmma::fill_fragment(acc[i][j], 0.f);

    for (int k0 = 0; k0 < Kd; k0 += 32) {
        // A tile 128x32
#pragma unroll
        for (int it = 0; it < 4; it++) {
            int lin = tid + it * 256;            // 0..1023
            int r = lin >> 3, c = (lin & 7) * 4;
            float4 f = *(const float4*)&A[(size_t)(m0 + r) * Kd + k0 + c];
            *(float4*)&As[r * 36 + c] = f;
        }
        // B tile 32x128
#pragma unroll
        for (int it = 0; it < 4; it++) {
            int lin = tid + it * 256;
            int r = lin >> 5, c = (lin & 31) * 4;
            float4 f = *(const float4*)&Bm[(size_t)(k0 + r) * N + n0 + c];
            *(float4*)&Bs[r * 132 + c] = f;
        }
        __syncthreads();
#pragma unroll
        for (int kk = 0; kk < 4; kk++) {
            wmma::fragment<wmma::matrix_a, 16, 16, 8, wmma::precision::tf32, wmma::row_major> af[4];
            wmma::fragment<wmma::matrix_b, 16, 16, 8, wmma::precision::tf32, wmma::row_major> bf[2];
#pragma unroll
            for (int i = 0; i < 4; i++) {
                wmma::load_matrix_sync(af[i], &As[(wr * 64 + i * 16) * 36 + kk * 8], 36);
#pragma unroll
                for (int t = 0; t < af[i].num_elements; t++)
                    af[i].x[t] = wmma::__float_to_tf32(af[i].x[t]);
            }
#pragma unroll
            for (int j = 0; j < 2; j++) {
                wmma::load_matrix_sync(bf[j], &Bs[(kk * 8) * 132 + wc * 32 + j * 16], 132);
#pragma unroll
                for (int t = 0; t < bf[j].num_elements; t++)
                    bf[j].x[t] = wmma::__float_to_tf32(bf[j].x[t]);
            }
#pragma unroll
            for (int i = 0; i < 4; i++)
#pragma unroll
                for (int j = 0; j < 2; j++)
                    wmma::mma_sync(acc[i][j], af[i], bf[j], acc[i][j]);
        }
        __syncthreads();
    }

    // stage C tile in smem (reuse), then epilogue with linear indexing
#pragma unroll
    for (int i = 0; i < 4; i++)
#pragma unroll
        for (int j = 0; j < 2; j++)
            wmma::store_matrix_sync(&sm[(wr * 64 + i * 16) * 132 + wc * 32 + j * 16],
                                    acc[i][j], 132, wmma::mem_row_major);
    __syncthreads();

#pragma unroll
    for (int it = 0; it < 64; it++) {
        int lin = tid + it * 256;               // 0..16383
        int r = lin >> 7, c = lin & 127;
        int row = m0 + r, col = n0 + c;
        float cv = sm[r * 132 + c] + bias[col];
        if (EPI == 1) cv = fmaxf(cv, 0.f);
        if (EPI == 2) {
            int b_ = row >> 12, sg = row & 4095;
            int w  = sg >> 9,   sl = sg & 511;
            int h  = col >> 8,  kd = col & 255;
            size_t idx = (((size_t)((b_ * NW + w) * HH + h)) * WINS + sl) * KD + kd;
            C[idx] = cv;
        } else {
            C[(size_t)row * N + col] = cv;
        }
    }
}

// ---------------- windowed attention (tensor-core) --------------------------
// grid: (WIN/64 = 8, B*NW*H = 128), 256 threads (8 warps)
// smem: sS[64][520] scores, sQV[64][260] (Q in ph1 / V chunks in ph2), sK[64][36]
#define SMEM_ATTN ((64*520 + 64*260 + 64*36) * 4)

__global__ __launch_bounds__(256)
void attn_tc(const float* __restrict__ q, const float* __restrict__ k,
             const float* __restrict__ v, float* __restrict__ ctx)
{
    extern __shared__ float sm[];
    float* sS = sm;                 // 64 x 520
    float* sQ = sm + 64 * 520;      // 64 x 260  (also V chunk 32 x 260)
    float* sK = sQ + 64 * 260;      // 64 x 36

    const int bwh = blockIdx.y;
    const int m0  = blockIdx.x * 64;
    const size_t base = (size_t)bwh * WINS * KD;
    const int tid = threadIdx.x;
    const int wid = tid >> 5;

    // load Q tile [64 x 256] row-major into sQ
#pragma unroll
    for (int it = 0; it < 16; it++) {
        int lin = tid + it * 256;               // 0..4095
        int r = lin >> 6, c = (lin & 63) * 4;
        float4 f = *(const float4*)&q[base + (size_t)(m0 + r) * KD + c];
        *(float4*)&sQ[r * 260 + c] = f;
    }
    __syncthreads();

    // ---- phase 1: scores = Q K^T / 16 ----
    // warp grid 4x2: wm = wid>>1 (16 rows each), wn = wid&1 (32 cols each)
    {
        const int wm = wid >> 1, wn = wid & 1;
        for (int nt = 0; nt < 8; nt++) {
            wmma::fragment<wmma::accumulator, 16, 16, 8, float> acc[2];
            wmma::fill_fragment(acc[0], 0.f);
            wmma::fill_fragment(acc[1], 0.f);

            for (int kc = 0; kc < 8; kc++) {
                // K chunk: 64 keys x 32 dims, row-major [key][kd]
#pragma unroll
                for (int it = 0; it < 2; it++) {
                    int lin = tid + it * 256;   // 0..511
                    int r = lin >> 3, c = (lin & 7) * 4;
                    float4 f = *(const float4*)&k[base + (size_t)(nt * 64 + r) * KD + kc * 32 + c];
                    *(float4*)&sK[r * 36 + c] = f;
                }
                __syncthreads();
#pragma unroll
                for (int kk = 0; kk < 4; kk++) {
                    wmma::fragment<wmma::matrix_a, 16, 16, 8, wmma::precision::tf32, wmma::row_major> af;
                    wmma::load_matrix_sync(af, &sQ[(wm * 16) * 260 + kc * 32 + kk * 8], 260);
#pragma unroll
                    for (int t = 0; t < af.num_elements; t++)
                        af.x[t] = wmma::__float_to_tf32(af.x[t]);
#pragma unroll
                    for (int j = 0; j < 2; j++) {
                        wmma::fragment<wmma::matrix_b, 16, 16, 8, wmma::precision::tf32, wmma::col_major> bf;
                        wmma::load_matrix_sync(bf, &sK[(wn * 32 + j * 16) * 36 + kk * 8], 36);
#pragma unroll
                        for (int t = 0; t < bf.num_elements; t++)
                            bf.x[t] = wmma::__float_to_tf32(bf.x[t]);
                        wmma::mma_sync(acc[j], af, bf, acc[j]);
                    }
                }
                __syncthreads();
            }
#pragma unroll
            for (int j = 0; j < 2; j++) {
#pragma unroll
                for (int t = 0; t < acc[j].num_elements; t++) acc[j].x[t] *= 0.0625f;
                wmma::store_matrix_sync(&sS[(wm * 16) * 520 + nt * 64 + wn * 32 + j * 16],
                                        acc[j], 520, wmma::mem_row_major);
            }
        }
    }
    __syncthreads();

    // ---- softmax: 8 warps x 8 rows ----
    {
        int lane = tid & 31;
        for (int rr = 0; rr < 8; rr++) {
            int r = wid * 8 + rr;
            float mx = -1e30f;
            for (int c = lane; c < 512; c += 32) mx = fmaxf(mx, sS[r * 520 + c]);
#pragma unroll
            for (int o = 16; o; o >>= 1) mx = fmaxf(mx, __shfl_xor_sync(0xffffffffu, mx, o));
            float sum = 0.f;
            for (int c = lane; c < 512; c += 32) {
                float e = expf(sS[r * 520 + c] - mx);
                sS[r * 520 + c] = e;
                sum += e;
            }
#pragma unroll
            for (int o = 16; o; o >>= 1) sum += __shfl_xor_sync(0xffffffffu, sum, o);
            float inv = 1.f / sum;
            for (int c = lane; c < 512; c += 32) sS[r * 520 + c] *= inv;
        }
    }

    // ---- phase 2: ctx = P @ V ----
    // warp grid 2x4: pm = wid>>2 (32 rows), pn = wid&3 (64 cols)
    {
        const int pm = wid >> 2, pn = wid & 3;
        float* sV = sQ;   // reuse Q region for V chunks [32][260]

        wmma::fragment<wmma::accumulator, 16, 16, 8, float> acc[2][4];
#pragma unroll
        for (int i = 0; i < 2; i++)
#pragma unroll
            for (int j = 0; j < 4; j++) wmma::fill_fragment(acc[i][j], 0.f);

        for (int kc = 0; kc < 16; kc++) {
            __syncthreads();   // prev chunk consumed (and softmax done on kc=0)
            // V chunk: 32 kv-rows x 256 kd
#pragma unroll
            for (int it = 0; it < 8; it++) {
                int lin = tid + it * 256;       // 0..2047
                int r = lin >> 6, c = (lin & 63) * 4;
                float4 f = *(const float4*)&v[base + (size_t)(kc * 32 + r) * KD + c];
                *(float4*)&sV[r * 260 + c] = f;
            }
            __syncthreads();
#pragma unroll
            for (int kk = 0; kk < 4; kk++) {
                wmma::fragment<wmma::matrix_a, 16, 16, 8, wmma::precision::tf32, wmma::row_major> af[2];
#pragma unroll
                for (int i = 0; i < 2; i++) {
                    wmma::load_matrix_sync(af[i], &sS[(pm * 32 + i * 16) * 520 + kc * 32 + kk * 8], 520);
#pragma unroll
                    for (int t = 0; t < af[i].num_elements; t++)
                        af[i].x[t] = wmma::__float_to_tf32(af[i].x[t]);
                }
#pragma unroll
                for (int j = 0; j < 4; j++) {
                    wmma::fragment<wmma::matrix_b, 16, 16, 8, wmma::precision::tf32, wmma::row_major> bf;
                    wmma::load_matrix_sync(bf, &sV[(kk * 8) * 260 + pn * 64 + j * 16], 260);
#pragma unroll
                    for (int t = 0; t < bf.num_elements; t++)
                        bf.x[t] = wmma::__float_to_tf32(bf.x[t]);
#pragma unroll
                    for (int i = 0; i < 2; i++)
                        wmma::mma_sync(acc[i][j], af[i], bf, acc[i][j]);
                }
            }
        }

        // write ctx: token-major [M, H*K], direct wmma stores (ld 512)
        const int b_ = bwh >> 4, w = (bwh >> 1) & 7, h = bwh & 1;
        const size_t tok0 = (size_t)b_ * SS + w * WINS + m0;
#pragma unroll
        for (int i = 0; i < 2; i++)
#pragma unroll
            for (int j = 0; j < 4; j++) {
                size_t row = tok0 + pm * 32 + i * 16;
                int col = h * KD + pn * 64 + j * 16;
                wmma::store_matrix_sync(&ctx[row * (HH * KD) + col], acc[i][j],
                                        HH * KD, wmma::mem_row_major);
            }
    }
}

// ---------------- residual + LayerNorm -------------------------------------
__global__ __launch_bounds__(256)
void ln_k(const float* __restrict__ a, const float* __restrict__ r,
          const float* __restrict__ g, const float* __restrict__ bta,
          float* __restrict__ out)
{
    int wid = threadIdx.x >> 5, lane = threadIdx.x & 31;
    size_t row = (size_t)blockIdx.x * 8 + wid;
    const float* pa = a + row * DD;
    const float* pr = r + row * DD;
    float v[8];
    float s = 0.f;
#pragma unroll
    for (int j = 0; j < 8; j++) {
        int c = lane + j * 32;
        v[j] = pa[c] + pr[c];
        s += v[j];
    }
#pragma unroll
    for (int o = 16; o; o >>= 1) s += __shfl_xor_sync(0xffffffffu, s, o);
    float mu = s * (1.f / 256.f);
    float vs = 0.f;
#pragma unroll
    for (int j = 0; j < 8; j++) {
        float d = v[j] - mu;
        vs += d * d;
    }
#pragma unroll
    for (int o = 16; o; o >>= 1) vs += __shfl_xor_sync(0xffffffffu, vs, o);
    float inv = rsqrtf(vs * (1.f / 256.f) + 1e-3f);
#pragma unroll
    for (int j = 0; j < 8; j++) {
        int c = lane + j * 32;
        out[row * DD + c] = (v[j] - mu) * inv * g[c] + bta[c];
    }
}

// ---------------- launch ----------------------------------------------------
extern "C" void kernel_launch(void* const* d_in, const int* in_sizes, int n_in,
                              void* d_out, int out_size)
{
    const float* x    = (const float*)d_in[0];
    const float* Wq   = (const float*)d_in[1];
    const float* bq   = (const float*)d_in[2];
    const float* Wk   = (const float*)d_in[3];
    const float* bk   = (const float*)d_in[4];
    const float* Wv   = (const float*)d_in[5];
    const float* bv   = (const float*)d_in[6];
    const float* Wo   = (const float*)d_in[7];
    const float* bo   = (const float*)d_in[8];
    const float* ln1g = (const float*)d_in[9];
    const float* ln1b = (const float*)d_in[10];
    const float* W1   = (const float*)d_in[11];
    const float* b1   = (const float*)d_in[12];
    const float* W2   = (const float*)d_in[13];
    const float* b2   = (const float*)d_in[14];
    const float* ln2g = (const float*)d_in[15];
    const float* ln2b = (const float*)d_in[16];

    float *q, *k, *v, *ctx, *y, *t, *hbuf;
    cudaGetSymbolAddress((void**)&q,    g_q);
    cudaGetSymbolAddress((void**)&k,    g_k);
    cudaGetSymbolAddress((void**)&v,    g_v);
    cudaGetSymbolAddress((void**)&ctx,  g_ctx);
    cudaGetSymbolAddress((void**)&y,    g_y);
    cudaGetSymbolAddress((void**)&t,    g_t);
    cudaGetSymbolAddress((void**)&hbuf, g_h);

    cudaFuncSetAttribute(attn_tc, cudaFuncAttributeMaxDynamicSharedMemorySize, SMEM_ATTN);
    cudaFuncSetAttribute(gemm_tc<0>, cudaFuncAttributeMaxDynamicSharedMemorySize, GEMM_SMEM);
    cudaFuncSetAttribute(gemm_tc<1>, cudaFuncAttributeMaxDynamicSharedMemorySize, GEMM_SMEM);
    cudaFuncSetAttribute(gemm_tc<2>, cudaFuncAttributeMaxDynamicSharedMemorySize, GEMM_SMEM);

    dim3 blk(256);

    // QKV projections (scatter into [b,w,h,s,k])
    gemm_tc<2><<<dim3(4, 256), blk, GEMM_SMEM>>>(x, Wq, bq, q, MTOK, HH * KD, DD);
    gemm_tc<2><<<dim3(4, 256), blk, GEMM_SMEM>>>(x, Wk, bk, k, MTOK, HH * KD, DD);
    gemm_tc<2><<<dim3(4, 256), blk, GEMM_SMEM>>>(x, Wv, bv, v, MTOK, HH * KD, DD);

    // windowed attention
    attn_tc<<<dim3(8, 128), blk, SMEM_ATTN>>>(q, k, v, ctx);

    // output projection + LN1
    gemm_tc<0><<<dim3(2, 256), blk, GEMM_SMEM>>>(ctx, Wo, bo, t, MTOK, DD, HH * KD);
    ln_k<<<MTOK / 8, blk>>>(t, x, ln1g, ln1b, y);

    // FFN
    gemm_tc<1><<<dim3(8, 256), blk, GEMM_SMEM>>>(y, W1, b1, hbuf, MTOK, DFF, DD);
    gemm_tc<0><<<dim3(2, 256), blk, GEMM_SMEM>>>(hbuf, W2, b2, t, MTOK, DD, DFF);
    ln_k<<<MTOK / 8, blk>>>(t, y, ln2g, ln2b, (float*)d_out);
}

// round 4
// speedup vs baseline: 2.3793x; 1.2634x over previous
#include <cuda_runtime.h>
#include <mma.h>
using namespace nvcuda;

// Problem constants
#define BB   8
#define SS   4096
#define DD   256
#define NW   8
#define WINS 512
#define HH   2
#define KD   256
#define DFF  1024
#define MTOK (BB*SS)          // 32768 tokens

// ---------------- device scratch (static allocation; no cudaMalloc) -------
__device__ float g_q  [(size_t)BB*SS*HH*KD];   // [b,w,h,s,k]
__device__ float g_k  [(size_t)BB*SS*HH*KD];
__device__ float g_v  [(size_t)BB*SS*HH*KD];
__device__ float g_ctx[(size_t)BB*SS*HH*KD];   // [token, h*K+k]
__device__ float g_y  [(size_t)MTOK*DD];       // post-LN1
__device__ float g_t  [(size_t)MTOK*DD];       // pre-LN scratch
__device__ float g_h  [(size_t)MTOK*DFF];      // FFN hidden

__device__ __forceinline__ float ftf(float x) {
    float y;
    asm("cvt.rna.tf32.f32 %0, %1;" : "=f"(y) : "f"(x));
    return y;
}

// ---------------- tf32 tensor-core GEMM ------------------------------------
// C[M,N] = A[M,Kd] @ B[Kd,N] + bias[N]; EPI: 0 plain, 1 relu, 2 qkv-scatter
// block tile 128x128, k-chunk 32, 8 warps (2x4), warp tile 64x32
// register double-buffered gmem->smem; tf32 rounding at smem store.
template<int EPI>
__global__ __launch_bounds__(256, 2)
void gemm_tc(const float* __restrict__ A, const float* __restrict__ Bm,
             const float* __restrict__ bias, float* __restrict__ C,
             int M, int N, int Kd)
{
    __shared__ float sg[8832];          // As[128][36] | Bs[32][132]; reused as se[64][132]
    float* As = sg;                      // 128*36 = 4608
    float* Bs = sg + 4608;               // 32*132 = 4224

    const int m0 = blockIdx.y * 128;
    const int n0 = blockIdx.x * 128;
    const int tid = threadIdx.x;
    const int wid = tid >> 5;
    const int wr = wid >> 2;     // 0..1 -> 64 rows
    const int wc = wid & 3;      // 0..3 -> 32 cols

    wmma::fragment<wmma::accumulator, 16, 16, 8, float> acc[4][2];
#pragma unroll
    for (int i = 0; i < 4; i++)
#pragma unroll
        for (int j = 0; j < 2; j++) wmma::fill_fragment(acc[i][j], 0.f);

    const int ar = tid >> 3, ac = (tid & 7) * 4;     // A: 128x32, 4 float4/thread
    const int br = tid >> 5, bc = (tid & 31) * 4;    // B: 32x128, 4 float4/thread

    float4 aR[4], bR[4];
    // preload chunk 0
#pragma unroll
    for (int it = 0; it < 4; it++) {
        aR[it] = *(const float4*)&A[(size_t)(m0 + ar + it * 32) * Kd + ac];
        bR[it] = *(const float4*)&Bm[(size_t)(br + it * 8) * N + n0 + bc];
    }

    const int nk = Kd >> 5;
    for (int c = 0; c < nk; c++) {
        // store staged regs -> smem with tf32 rounding
#pragma unroll
        for (int it = 0; it < 4; it++) {
            float* d = &As[(ar + it * 32) * 36 + ac];
            d[0] = ftf(aR[it].x); d[1] = ftf(aR[it].y);
            d[2] = ftf(aR[it].z); d[3] = ftf(aR[it].w);
            float* e = &Bs[(br + it * 8) * 132 + bc];
            e[0] = ftf(bR[it].x); e[1] = ftf(bR[it].y);
            e[2] = ftf(bR[it].z); e[3] = ftf(bR[it].w);
        }
        __syncthreads();
        // issue next chunk loads (overlap with compute below)
        if (c + 1 < nk) {
            int k0 = (c + 1) * 32;
#pragma unroll
            for (int it = 0; it < 4; it++) {
                aR[it] = *(const float4*)&A[(size_t)(m0 + ar + it * 32) * Kd + k0 + ac];
                bR[it] = *(const float4*)&Bm[(size_t)(k0 + br + it * 8) * N + n0 + bc];
            }
        }
        // compute
#pragma unroll
        for (int kk = 0; kk < 4; kk++) {
            wmma::fragment<wmma::matrix_b, 16, 16, 8, wmma::precision::tf32, wmma::row_major> bf[2];
#pragma unroll
            for (int j = 0; j < 2; j++)
                wmma::load_matrix_sync(bf[j], &Bs[(kk * 8) * 132 + wc * 32 + j * 16], 132);
#pragma unroll
            for (int i = 0; i < 4; i++) {
                wmma::fragment<wmma::matrix_a, 16, 16, 8, wmma::precision::tf32, wmma::row_major> af;
                wmma::load_matrix_sync(af, &As[(wr * 64 + i * 16) * 36 + kk * 8], 36);
#pragma unroll
                for (int j = 0; j < 2; j++)
                    wmma::mma_sync(acc[i][j], af, bf[j], acc[i][j]);
            }
        }
        __syncthreads();
    }

    // epilogue in two 64-row halves staged through smem
    float* se = sg;   // 64 x 132
#pragma unroll
    for (int h = 0; h < 2; h++) {
        if (wr == h) {
#pragma unroll
            for (int i = 0; i < 4; i++)
#pragma unroll
                for (int j = 0; j < 2; j++)
                    wmma::store_matrix_sync(&se[(i * 16) * 132 + wc * 32 + j * 16],
                                            acc[i][j], 132, wmma::mem_row_major);
        }
        __syncthreads();
#pragma unroll
        for (int it = 0; it < 32; it++) {
            int lin = tid + it * 256;           // 0..8191 (64x128)
            int r = lin >> 7, cc = lin & 127;
            int row = m0 + h * 64 + r, col = n0 + cc;
            float cv = se[r * 132 + cc] + bias[col];
            if (EPI == 1) cv = fmaxf(cv, 0.f);
            if (EPI == 2) {
                int b_ = row >> 12, sgx = row & 4095;
                int w  = sgx >> 9,  sl = sgx & 511;
                int hh = col >> 8,  kd = col & 255;
                size_t idx = (((size_t)((b_ * NW + w) * HH + hh)) * WINS + sl) * KD + kd;
                C[idx] = cv;
            } else {
                C[(size_t)row * N + col] = cv;
            }
        }
        __syncthreads();
    }
}

// ---------------- windowed attention (tensor-core, 32-query tiles) ----------
// grid: (WIN/32 = 16, B*NW*H = 128), 256 threads (8 warps)
// smem: sS[32][516] | sK[512][20] | sQc[32][20]  (sV[32][260] aliases sK)
#define SMEM_ATTN ((32*516 + 512*20 + 32*20) * 4)

__global__ __launch_bounds__(256, 2)
void attn_tc(const float* __restrict__ q, const float* __restrict__ k,
             const float* __restrict__ v, float* __restrict__ ctx)
{
    extern __shared__ float sm[];
    float* sS  = sm;                     // 32 x 516
    float* sK  = sm + 32 * 516;          // 512 x 20
    float* sQc = sK + 512 * 20;          // 32 x 20

    const int bwh = blockIdx.y;
    const int m0  = blockIdx.x * 32;
    const size_t base = (size_t)bwh * WINS * KD;
    const int tid = threadIdx.x;
    const int wid = tid >> 5;
    const int lane = tid & 31;

    // ---- phase 1: S = Q K^T / 16 with row of S resident in registers ----
    {
        const int wm = wid >> 2;    // 0..1 : 16-row group
        const int wc = wid & 3;     // 0..3 : 128-col group

        wmma::fragment<wmma::accumulator, 16, 16, 8, float> acc[8];
#pragma unroll
        for (int nb = 0; nb < 8; nb++) wmma::fill_fragment(acc[nb], 0.f);

        for (int kc = 0; kc < 16; kc++) {           // 16-dim chunks of KD
            // Q chunk 32x16
            if (tid < 128) {
                int r = tid >> 2, c4 = (tid & 3) * 4;
                float4 f = *(const float4*)&q[base + (size_t)(m0 + r) * KD + kc * 16 + c4];
                float* d = &sQc[r * 20 + c4];
                d[0] = ftf(f.x); d[1] = ftf(f.y); d[2] = ftf(f.z); d[3] = ftf(f.w);
            }
            // K chunk 512x16
#pragma unroll
            for (int it = 0; it < 8; it++) {
                int lin = tid + it * 256;
                int r = lin >> 2, c4 = (lin & 3) * 4;
                float4 f = *(const float4*)&k[base + (size_t)r * KD + kc * 16 + c4];
                float* d = &sK[r * 20 + c4];
                d[0] = ftf(f.x); d[1] = ftf(f.y); d[2] = ftf(f.z); d[3] = ftf(f.w);
            }
            __syncthreads();
#pragma unroll
            for (int kk = 0; kk < 2; kk++) {
                wmma::fragment<wmma::matrix_a, 16, 16, 8, wmma::precision::tf32, wmma::row_major> af;
                wmma::load_matrix_sync(af, &sQc[(wm * 16) * 20 + kk * 8], 20);
#pragma unroll
                for (int nb = 0; nb < 8; nb++) {
                    wmma::fragment<wmma::matrix_b, 16, 16, 8, wmma::precision::tf32, wmma::col_major> bf;
                    wmma::load_matrix_sync(bf, &sK[(wc * 128 + nb * 16) * 20 + kk * 8], 20);
                    wmma::mma_sync(acc[nb], af, bf, acc[nb]);
                }
            }
            __syncthreads();
        }
        // scale + dump to score strip
#pragma unroll
        for (int nb = 0; nb < 8; nb++) {
#pragma unroll
            for (int t = 0; t < acc[nb].num_elements; t++) acc[nb].x[t] *= 0.0625f;
            wmma::store_matrix_sync(&sS[(wm * 16) * 516 + wc * 128 + nb * 16],
                                    acc[nb], 516, wmma::mem_row_major);
        }
    }
    __syncthreads();

    // ---- softmax: 8 warps x 4 rows; writes tf32-rounded probabilities ----
#pragma unroll
    for (int rr = 0; rr < 4; rr++) {
        int r = wid * 4 + rr;
        float mx = -1e30f;
        for (int c = lane; c < 512; c += 32) mx = fmaxf(mx, sS[r * 516 + c]);
#pragma unroll
        for (int o = 16; o; o >>= 1) mx = fmaxf(mx, __shfl_xor_sync(0xffffffffu, mx, o));
        float sum = 0.f;
        for (int c = lane; c < 512; c += 32) {
            float e = expf(sS[r * 516 + c] - mx);
            sS[r * 516 + c] = e;
            sum += e;
        }
#pragma unroll
        for (int o = 16; o; o >>= 1) sum += __shfl_xor_sync(0xffffffffu, sum, o);
        float inv = 1.f / sum;
        for (int c = lane; c < 512; c += 32) sS[r * 516 + c] = ftf(sS[r * 516 + c] * inv);
    }
    __syncthreads();

    // ---- phase 2: ctx = P @ V ----
    {
        const int wm2 = wid >> 2;    // 0..1 : 16-row group
        const int wc2 = wid & 3;     // 0..3 : 64-col group
        float* sV = sK;              // 32 x 260 chunk (aliases K region)

        wmma::fragment<wmma::accumulator, 16, 16, 8, float> acc2[4];
#pragma unroll
        for (int j = 0; j < 4; j++) wmma::fill_fragment(acc2[j], 0.f);

        for (int kc = 0; kc < 16; kc++) {           // 32-key chunks
            // V chunk 32x256
#pragma unroll
            for (int it = 0; it < 8; it++) {
                int lin = tid + it * 256;
                int r = lin >> 6, c4 = (lin & 63) * 4;
                float4 f = *(const float4*)&v[base + (size_t)(kc * 32 + r) * KD + c4];
                float* d = &sV[r * 260 + c4];
                d[0] = ftf(f.x); d[1] = ftf(f.y); d[2] = ftf(f.z); d[3] = ftf(f.w);
            }
            __syncthreads();
#pragma unroll
            for (int kk = 0; kk < 4; kk++) {
                wmma::fragment<wmma::matrix_a, 16, 16, 8, wmma::precision::tf32, wmma::row_major> af;
                wmma::load_matrix_sync(af, &sS[(wm2 * 16) * 516 + kc * 32 + kk * 8], 516);
#pragma unroll
                for (int j = 0; j < 4; j++) {
                    wmma::fragment<wmma::matrix_b, 16, 16, 8, wmma::precision::tf32, wmma::row_major> bf;
                    wmma::load_matrix_sync(bf, &sV[(kk * 8) * 260 + wc2 * 64 + j * 16], 260);
                    wmma::mma_sync(acc2[j], af, bf, acc2[j]);
                }
            }
            __syncthreads();
        }

        // write ctx: token-major [M, H*K]
        const int b_ = bwh >> 4, w = (bwh >> 1) & 7, h = bwh & 1;
        const size_t tok0 = (size_t)b_ * SS + w * WINS + m0;
#pragma unroll
        for (int j = 0; j < 4; j++) {
            size_t row = tok0 + wm2 * 16;
            int col = h * KD + wc2 * 64 + j * 16;
            wmma::store_matrix_sync(&ctx[row * (HH * KD) + col], acc2[j],
                                    HH * KD, wmma::mem_row_major);
        }
    }
}

// ---------------- residual + LayerNorm -------------------------------------
__global__ __launch_bounds__(256)
void ln_k(const float* __restrict__ a, const float* __restrict__ r,
          const float* __restrict__ g, const float* __restrict__ bta,
          float* __restrict__ out)
{
    int wid = threadIdx.x >> 5, lane = threadIdx.x & 31;
    size_t row = (size_t)blockIdx.x * 8 + wid;
    const float* pa = a + row * DD;
    const float* pr = r + row * DD;
    float v[8];
    float s = 0.f;
#pragma unroll
    for (int j = 0; j < 8; j++) {
        int c = lane + j * 32;
        v[j] = pa[c] + pr[c];
        s += v[j];
    }
#pragma unroll
    for (int o = 16; o; o >>= 1) s += __shfl_xor_sync(0xffffffffu, s, o);
    float mu = s * (1.f / 256.f);
    float vs = 0.f;
#pragma unroll
    for (int j = 0; j < 8; j++) {
        float d = v[j] - mu;
        vs += d * d;
    }
#pragma unroll
    for (int o = 16; o; o >>= 1) vs += __shfl_xor_sync(0xffffffffu, vs, o);
    float inv = rsqrtf(vs * (1.f / 256.f) + 1e-3f);
#pragma unroll
    for (int j = 0; j < 8; j++) {
        int c = lane + j * 32;
        out[row * DD + c] = (v[j] - mu) * inv * g[c] + bta[c];
    }
}

// ---------------- launch ----------------------------------------------------
extern "C" void kernel_launch(void* const* d_in, const int* in_sizes, int n_in,
                              void* d_out, int out_size)
{
    const float* x    = (const float*)d_in[0];
    const float* Wq   = (const float*)d_in[1];
    const float* bq   = (const float*)d_in[2];
    const float* Wk   = (const float*)d_in[3];
    const float* bk   = (const float*)d_in[4];
    const float* Wv   = (const float*)d_in[5];
    const float* bv   = (const float*)d_in[6];
    const float* Wo   = (const float*)d_in[7];
    const float* bo   = (const float*)d_in[8];
    const float* ln1g = (const float*)d_in[9];
    const float* ln1b = (const float*)d_in[10];
    const float* W1   = (const float*)d_in[11];
    const float* b1   = (const float*)d_in[12];
    const float* W2   = (const float*)d_in[13];
    const float* b2   = (const float*)d_in[14];
    const float* ln2g = (const float*)d_in[15];
    const float* ln2b = (const float*)d_in[16];

    float *q, *k, *v, *ctx, *y, *t, *hbuf;
    cudaGetSymbolAddress((void**)&q,    g_q);
    cudaGetSymbolAddress((void**)&k,    g_k);
    cudaGetSymbolAddress((void**)&v,    g_v);
    cudaGetSymbolAddress((void**)&ctx,  g_ctx);
    cudaGetSymbolAddress((void**)&y,    g_y);
    cudaGetSymbolAddress((void**)&t,    g_t);
    cudaGetSymbolAddress((void**)&hbuf, g_h);

    cudaFuncSetAttribute(attn_tc, cudaFuncAttributeMaxDynamicSharedMemorySize, SMEM_ATTN);

    dim3 blk(256);

    // QKV projections (scatter into [b,w,h,s,k])
    gemm_tc<2><<<dim3(4, 256), blk>>>(x, Wq, bq, q, MTOK, HH * KD, DD);
    gemm_tc<2><<<dim3(4, 256), blk>>>(x, Wk, bk, k, MTOK, HH * KD, DD);
    gemm_tc<2><<<dim3(4, 256), blk>>>(x, Wv, bv, v, MTOK, HH * KD, DD);

    // windowed attention
    attn_tc<<<dim3(16, 128), blk, SMEM_ATTN>>>(q, k, v, ctx);

    // output projection + LN1
    gemm_tc<0><<<dim3(2, 256), blk>>>(ctx, Wo, bo, t, MTOK, DD, HH * KD);
    ln_k<<<MTOK / 8, blk>>>(t, x, ln1g, ln1b, y);

    // FFN
    gemm_tc<1><<<dim3(8, 256), blk>>>(y, W1, b1, hbuf, MTOK, DFF, DD);
    gemm_tc<0><<<dim3(2, 256), blk>>>(hbuf, W2, b2, t, MTOK, DD, DFF);
    ln_k<<<MTOK / 8, blk>>>(t, y, ln2g, ln2b, (float*)d_out);
}

// round 8
// speedup vs baseline: 2.5647x; 1.0779x over previous
#include <cuda_runtime.h>
#include <cstdint>
#include <mma.h>
using namespace nvcuda;

// Problem constants
#define BB   8
#define SS   4096
#define DD   256
#define NW   8
#define WINS 512
#define HH   2
#define KD   256
#define DFF  1024
#define MTOK (BB*SS)          // 32768 tokens

// ---------------- device scratch (static allocation; no cudaMalloc) -------
__device__ float g_q  [(size_t)BB*SS*HH*KD];   // [b,w,h,s,k]
__device__ float g_k  [(size_t)BB*SS*HH*KD];
__device__ float g_v  [(size_t)BB*SS*HH*KD];
__device__ float g_ctx[(size_t)BB*SS*HH*KD];   // [token, h*K+k]
__device__ float g_y  [(size_t)MTOK*DD];       // post-LN1
__device__ float g_t  [(size_t)MTOK*DD];       // pre-LN scratch
__device__ float g_h  [(size_t)MTOK*DFF];      // FFN hidden

// ---------------- cp.async helpers -----------------------------------------
__device__ __forceinline__ void cpa16(float* smem, const float* g) {
    unsigned int s = (unsigned int)__cvta_generic_to_shared(smem);
    asm volatile("cp.async.cg.shared.global [%0], [%1], 16;" :: "r"(s), "l"(g));
}
#define CPA_COMMIT() asm volatile("cp.async.commit_group;")
#define CPA_WAIT1()  asm volatile("cp.async.wait_group 1;")
#define CPA_WAIT0()  asm volatile("cp.async.wait_group 0;")

// ---------------- tf32 tensor-core GEMM (cp.async 2-stage pipeline) --------
// C[M,N] = A[M,Kd] @ B[Kd,N] + bias[N]; EPI: 0 plain, 1 relu, 2 qkv-scatter
// block tile 128x128, k-chunk 32, 8 warps (2x4), warp tile 64x32.
// fp32 bits fed to HMMA directly (hardware tf32 truncation).
#define GSTG  8832                    // floats per stage: As 128*36 + Bs 32*132
#define GEMM_SMEM (2*GSTG*4)

template<int EPI>
__global__ __launch_bounds__(256, 2)
void gemm_tc(const float* __restrict__ A, const float* __restrict__ Bm,
             const float* __restrict__ bias, float* __restrict__ C,
             int M, int N, int Kd)
{
    extern __shared__ float sg[];

    const int m0 = blockIdx.y * 128;
    const int n0 = blockIdx.x * 128;
    const int tid = threadIdx.x;
    const int wid = tid >> 5;
    const int wr = wid >> 2;     // 0..1 -> 64 rows
    const int wc = wid & 3;      // 0..3 -> 32 cols

    const int ar = tid >> 3, ac = (tid & 7) * 4;     // A: 128x32
    const int br = tid >> 5, bc = (tid & 31) * 4;    // B: 32x128

    wmma::fragment<wmma::accumulator, 16, 16, 8, float> acc[4][2];
#pragma unroll
    for (int i = 0; i < 4; i++)
#pragma unroll
        for (int j = 0; j < 2; j++) wmma::fill_fragment(acc[i][j], 0.f);

    const int nk = Kd >> 5;

    // stage loader
    auto load_stage = [&](int s, int k0) {
        float* As = sg + s * GSTG;
        float* Bs = As + 4608;
#pragma unroll
        for (int it = 0; it < 4; it++)
            cpa16(&As[(ar + it * 32) * 36 + ac],
                  &A[(size_t)(m0 + ar + it * 32) * Kd + k0 + ac]);
#pragma unroll
        for (int it = 0; it < 4; it++)
            cpa16(&Bs[(br + it * 8) * 132 + bc],
                  &Bm[(size_t)(k0 + br + it * 8) * N + n0 + bc]);
    };

    load_stage(0, 0);  CPA_COMMIT();
    load_stage(1, 32); CPA_COMMIT();

    for (int c = 0; c < nk; c++) {
        // Drain rule: on the final chunk the newest committed group IS the
        // stage we're about to read, so wait for ALL groups there.
        if (c + 1 < nk) { CPA_WAIT1(); } else { CPA_WAIT0(); }
        __syncthreads();
        float* As = sg + (c & 1) * GSTG;
        float* Bs = As + 4608;
#pragma unroll
        for (int kk = 0; kk < 4; kk++) {
            wmma::fragment<wmma::matrix_b, 16, 16, 8, wmma::precision::tf32, wmma::row_major> bf[2];
#pragma unroll
            for (int j = 0; j < 2; j++)
                wmma::load_matrix_sync(bf[j], &Bs[(kk * 8) * 132 + wc * 32 + j * 16], 132);
#pragma unroll
            for (int i = 0; i < 4; i++) {
                wmma::fragment<wmma::matrix_a, 16, 16, 8, wmma::precision::tf32, wmma::row_major> af;
                wmma::load_matrix_sync(af, &As[(wr * 64 + i * 16) * 36 + kk * 8], 36);
#pragma unroll
                for (int j = 0; j < 2; j++)
                    wmma::mma_sync(acc[i][j], af, bf[j], acc[i][j]);
            }
        }
        __syncthreads();
        if (c + 2 < nk) { load_stage(c & 1, (c + 2) * 32); CPA_COMMIT(); }
    }

    // epilogue in two 64-row halves staged through smem (stage-0 region)
    float* se = sg;   // 64 x 132
#pragma unroll
    for (int h = 0; h < 2; h++) {
        if (wr == h) {
#pragma unroll
            for (int i = 0; i < 4; i++)
#pragma unroll
                for (int j = 0; j < 2; j++)
                    wmma::store_matrix_sync(&se[(i * 16) * 132 + wc * 32 + j * 16],
                                            acc[i][j], 132, wmma::mem_row_major);
        }
        __syncthreads();
#pragma unroll
        for (int it = 0; it < 32; it++) {
            int lin = tid + it * 256;           // 0..8191 (64x128)
            int r = lin >> 7, cc = lin & 127;
            int row = m0 + h * 64 + r, col = n0 + cc;
            float cv = se[r * 132 + cc] + bias[col];
            if (EPI == 1) cv = fmaxf(cv, 0.f);
            if (EPI == 2) {
                int b_ = row >> 12, sgx = row & 4095;
                int w  = sgx >> 9,  sl = sgx & 511;
                int hh = col >> 8,  kd = col & 255;
                size_t idx = (((size_t)((b_ * NW + w) * HH + hh)) * WINS + sl) * KD + kd;
                C[idx] = cv;
            } else {
                C[(size_t)row * N + col] = cv;
            }
        }
        __syncthreads();
    }
}

// ---------------- windowed attention (tensor-core, 32-query tiles) ----------
// grid: (WIN/32 = 16, B*NW*H = 128), 256 threads (8 warps)
// smem: sS[32][516] | sK[512][20] | sQc[32][20]; phase-2 per-warp V tiles
// alias onto the sK region (8 warps x 16 x 68 floats).
#define SMEM_ATTN ((32*516 + 512*20 + 32*20) * 4)

__global__ __launch_bounds__(256, 2)
void attn_tc(const float* __restrict__ q, const float* __restrict__ k,
             const float* __restrict__ v, float* __restrict__ ctx)
{
    extern __shared__ float sm[];
    float* sS  = sm;                     // 32 x 516
    float* sK  = sm + 32 * 516;          // 512 x 20
    float* sQc = sK + 512 * 20;          // 32 x 20

    const int bwh = blockIdx.y;
    const int m0  = blockIdx.x * 32;
    const size_t base = (size_t)bwh * WINS * KD;
    const int tid = threadIdx.x;
    const int wid = tid >> 5;
    const int lane = tid & 31;

    // ---- phase 1: S = Q K^T / 16, full 512-key row of S in registers ----
    {
        const int wm = wid >> 2;    // 0..1 : 16-row group
        const int wc = wid & 3;     // 0..3 : 128-col group

        wmma::fragment<wmma::accumulator, 16, 16, 8, float> acc[8];
#pragma unroll
        for (int nb = 0; nb < 8; nb++) wmma::fill_fragment(acc[nb], 0.f);

        for (int kc = 0; kc < 16; kc++) {           // 16-dim chunks of KD
            // Q chunk 32x16
            if (tid < 128) {
                int r = tid >> 2, c4 = (tid & 3) * 4;
                float4 f = *(const float4*)&q[base + (size_t)(m0 + r) * KD + kc * 16 + c4];
                *(float4*)&sQc[r * 20 + c4] = f;
            }
            // K chunk 512x16
#pragma unroll
            for (int it = 0; it < 8; it++) {
                int lin = tid + it * 256;
                int r = lin >> 2, c4 = (lin & 3) * 4;
                float4 f = *(const float4*)&k[base + (size_t)r * KD + kc * 16 + c4];
                *(float4*)&sK[r * 20 + c4] = f;
            }
            __syncthreads();
#pragma unroll
            for (int kk = 0; kk < 2; kk++) {
                wmma::fragment<wmma::matrix_a, 16, 16, 8, wmma::precision::tf32, wmma::row_major> af;
                wmma::load_matrix_sync(af, &sQc[(wm * 16) * 20 + kk * 8], 20);
#pragma unroll
                for (int nb = 0; nb < 8; nb++) {
                    wmma::fragment<wmma::matrix_b, 16, 16, 8, wmma::precision::tf32, wmma::col_major> bf;
                    wmma::load_matrix_sync(bf, &sK[(wc * 128 + nb * 16) * 20 + kk * 8], 20);
                    wmma::mma_sync(acc[nb], af, bf, acc[nb]);
                }
            }
            __syncthreads();
        }
        // scale + dump to score strip
#pragma unroll
        for (int nb = 0; nb < 8; nb++) {
#pragma unroll
            for (int t = 0; t < acc[nb].num_elements; t++) acc[nb].x[t] *= 0.0625f;
            wmma::store_matrix_sync(&sS[(wm * 16) * 516 + wc * 128 + nb * 16],
                                    acc[nb], 516, wmma::mem_row_major);
        }
    }
    __syncthreads();

    // ---- softmax: 8 warps x 4 rows ----
#pragma unroll
    for (int rr = 0; rr < 4; rr++) {
        int r = wid * 4 + rr;
        float mx = -1e30f;
        for (int c = lane; c < 512; c += 32) mx = fmaxf(mx, sS[r * 516 + c]);
#pragma unroll
        for (int o = 16; o; o >>= 1) mx = fmaxf(mx, __shfl_xor_sync(0xffffffffu, mx, o));
        float sum = 0.f;
        for (int c = lane; c < 512; c += 32) {
            float e = expf(sS[r * 516 + c] - mx);
            sS[r * 516 + c] = e;
            sum += e;
        }
#pragma unroll
        for (int o = 16; o; o >>= 1) sum += __shfl_xor_sync(0xffffffffu, sum, o);
        float inv = 1.f / sum;
        for (int c = lane; c < 512; c += 32) sS[r * 516 + c] *= inv;
    }
    __syncthreads();   // scores final; sK region free for per-warp V tiles

    // ---- phase 2: ctx = P @ V, per-warp V tiles, warp-local sync only ----
    {
        const int wm2 = wid >> 2;    // 0..1 : 16-row group of P
        const int wc2 = wid & 3;     // 0..3 : 64-col group of V
        float* sVw = sK + wid * (16 * 68);   // warp-private 16 x 68

        wmma::fragment<wmma::accumulator, 16, 16, 8, float> acc2[4];
#pragma unroll
        for (int j = 0; j < 4; j++) wmma::fill_fragment(acc2[j], 0.f);

        for (int kc = 0; kc < 32; kc++) {           // 16-key chunks
            // warp loads its 16x64 V slice
#pragma unroll
            for (int it = 0; it < 8; it++) {
                int lin = lane + it * 32;            // 0..255
                int r = lin >> 4, c4 = (lin & 15) * 4;
                float4 f = *(const float4*)&v[base + (size_t)(kc * 16 + r) * KD + wc2 * 64 + c4];
                *(float4*)&sVw[r * 68 + c4] = f;
            }
            __syncwarp();
#pragma unroll
            for (int kk = 0; kk < 2; kk++) {
                wmma::fragment<wmma::matrix_a, 16, 16, 8, wmma::precision::tf32, wmma::row_major> af;
                wmma::load_matrix_sync(af, &sS[(wm2 * 16) * 516 + kc * 16 + kk * 8], 516);
#pragma unroll
                for (int j = 0; j < 4; j++) {
                    wmma::fragment<wmma::matrix_b, 16, 16, 8, wmma::precision::tf32, wmma::row_major> bf;
                    wmma::load_matrix_sync(bf, &sVw[(kk * 8) * 68 + j * 16], 68);
                    wmma::mma_sync(acc2[j], af, bf, acc2[j]);
                }
            }
            __syncwarp();
        }

        // write ctx: token-major [M, H*K]
        const int b_ = bwh >> 4, w = (bwh >> 1) & 7, h = bwh & 1;
        const size_t tok0 = (size_t)b_ * SS + w * WINS + m0;
#pragma unroll
        for (int j = 0; j < 4; j++) {
            size_t row = tok0 + wm2 * 16;
            int col = h * KD + wc2 * 64 + j * 16;
            wmma::store_matrix_sync(&ctx[row * (HH * KD) + col], acc2[j],
                                    HH * KD, wmma::mem_row_major);
        }
    }
}

// ---------------- residual + LayerNorm -------------------------------------
__global__ __launch_bounds__(256)
void ln_k(const float* __restrict__ a, const float* __restrict__ r,
          const float* __restrict__ g, const float* __restrict__ bta,
          float* __restrict__ out)
{
    int wid = threadIdx.x >> 5, lane = threadIdx.x & 31;
    size_t row = (size_t)blockIdx.x * 8 + wid;
    const float* pa = a + row * DD;
    const float* pr = r + row * DD;
    float v[8];
    float s = 0.f;
#pragma unroll
    for (int j = 0; j < 8; j++) {
        int c = lane + j * 32;
        v[j] = pa[c] + pr[c];
        s += v[j];
    }
#pragma unroll
    for (int o = 16; o; o >>= 1) s += __shfl_xor_sync(0xffffffffu, s, o);
    float mu = s * (1.f / 256.f);
    float vs = 0.f;
#pragma unroll
    for (int j = 0; j < 8; j++) {
        float d = v[j] - mu;
        vs += d * d;
    }
#pragma unroll
    for (int o = 16; o; o >>= 1) vs += __shfl_xor_sync(0xffffffffu, vs, o);
    float inv = rsqrtf(vs * (1.f / 256.f) + 1e-3f);
#pragma unroll
    for (int j = 0; j < 8; j++) {
        int c = lane + j * 32;
        out[row * DD + c] = (v[j] - mu) * inv * g[c] + bta[c];
    }
}

// ---------------- launch ----------------------------------------------------
extern "C" void kernel_launch(void* const* d_in, const int* in_sizes, int n_in,
                              void* d_out, int out_size)
{
    const float* x    = (const float*)d_in[0];
    const float* Wq   = (const float*)d_in[1];
    const float* bq   = (const float*)d_in[2];
    const float* Wk   = (const float*)d_in[3];
    const float* bk   = (const float*)d_in[4];
    const float* Wv   = (const float*)d_in[5];
    const float* bv   = (const float*)d_in[6];
    const float* Wo   = (const float*)d_in[7];
    const float* bo   = (const float*)d_in[8];
    const float* ln1g = (const float*)d_in[9];
    const float* ln1b = (const float*)d_in[10];
    const float* W1   = (const float*)d_in[11];
    const float* b1   = (const float*)d_in[12];
    const float* W2   = (const float*)d_in[13];
    const float* b2   = (const float*)d_in[14];
    const float* ln2g = (const float*)d_in[15];
    const float* ln2b = (const float*)d_in[16];

    float *q, *k, *v, *ctx, *y, *t, *hbuf;
    cudaGetSymbolAddress((void**)&q,    g_q);
    cudaGetSymbolAddress((void**)&k,    g_k);
    cudaGetSymbolAddress((void**)&v,    g_v);
    cudaGetSymbolAddress((void**)&ctx,  g_ctx);
    cudaGetSymbolAddress((void**)&y,    g_y);
    cudaGetSymbolAddress((void**)&t,    g_t);
    cudaGetSymbolAddress((void**)&hbuf, g_h);

    cudaFuncSetAttribute(attn_tc, cudaFuncAttributeMaxDynamicSharedMemorySize, SMEM_ATTN);
    cudaFuncSetAttribute(gemm_tc<0>, cudaFuncAttributeMaxDynamicSharedMemorySize, GEMM_SMEM);
    cudaFuncSetAttribute(gemm_tc<1>, cudaFuncAttributeMaxDynamicSharedMemorySize, GEMM_SMEM);
    cudaFuncSetAttribute(gemm_tc<2>, cudaFuncAttributeMaxDynamicSharedMemorySize, GEMM_SMEM);

    dim3 blk(256);

    // QKV projections (scatter into [b,w,h,s,k])
    gemm_tc<2><<<dim3(4, 256), blk, GEMM_SMEM>>>(x, Wq, bq, q, MTOK, HH * KD, DD);
    gemm_tc<2><<<dim3(4, 256), blk, GEMM_SMEM>>>(x, Wk, bk, k, MTOK, HH * KD, DD);
    gemm_tc<2><<<dim3(4, 256), blk, GEMM_SMEM>>>(x, Wv, bv, v, MTOK, HH * KD, DD);

    // windowed attention
    attn_tc<<<dim3(16, 128), blk, SMEM_ATTN>>>(q, k, v, ctx);

    // output projection + LN1
    gemm_tc<0><<<dim3(2, 256), blk, GEMM_SMEM>>>(ctx, Wo, bo, t, MTOK, DD, HH * KD);
    ln_k<<<MTOK / 8, blk>>>(t, x, ln1g, ln1b, y);

    // FFN
    gemm_tc<1><<<dim3(8, 256), blk, GEMM_SMEM>>>(y, W1, b1, hbuf, MTOK, DFF, DD);
    gemm_tc<0><<<dim3(2, 256), blk, GEMM_SMEM>>>(hbuf, W2, b2, t, MTOK, DD, DFF);
    ln_k<<<MTOK / 8, blk>>>(t, y, ln2g, ln2b, (float*)d_out);
}

// round 10
// speedup vs baseline: 2.8070x; 1.0945x over previous
#include <cuda_runtime.h>
#include <cstdint>
#include <mma.h>
using namespace nvcuda;

// Problem constants
#define BB   8
#define SS   4096
#define DD   256
#define NW   8
#define WINS 512
#define HH   2
#define KD   256
#define DFF  1024
#define MTOK (BB*SS)          // 32768 tokens

// ---------------- device scratch (static allocation; no cudaMalloc) -------
__device__ float g_q  [(size_t)BB*SS*HH*KD];   // [b,w,h,s,k]
__device__ float g_k  [(size_t)BB*SS*HH*KD];
__device__ float g_v  [(size_t)BB*SS*HH*KD];
__device__ float g_ctx[(size_t)BB*SS*HH*KD];   // [token, h*K+k]
__device__ float g_y  [(size_t)MTOK*DD];       // post-LN1
__device__ float g_t  [(size_t)MTOK*DD];       // pre-LN scratch
__device__ float g_h  [(size_t)MTOK*DFF];      // FFN hidden

// ---------------- cp.async helpers -----------------------------------------
__device__ __forceinline__ void cpa16(float* smem, const float* g) {
    unsigned int s = (unsigned int)__cvta_generic_to_shared(smem);
    asm volatile("cp.async.cg.shared.global [%0], [%1], 16;" :: "r"(s), "l"(g));
}
#define CPA_COMMIT() asm volatile("cp.async.commit_group;")
#define CPA_WAIT2()  asm volatile("cp.async.wait_group 2;")
#define CPA_WAIT1()  asm volatile("cp.async.wait_group 1;")
#define CPA_WAIT0()  asm volatile("cp.async.wait_group 0;")

// ---------------- tf32 tensor-core GEMM (cp.async 3-stage pipeline) --------
// C[M,N] = A[M,Kd] @ B[Kd,N] + bias[N]; EPI: 0 plain, 1 relu, 2 qkv-scatter
// block tile 128x128, k-chunk 32, 8 warps (2x4), warp tile 64x32.
#define GSTG  8832                    // floats per stage: As 128*36 + Bs 32*132
#define GEMM_SMEM (3*GSTG*4)          // 105,984 B -> 2 CTAs/SM

template<int EPI>
__device__ __forceinline__
void gemm_body(const float* __restrict__ A, const float* __restrict__ Bm,
               const float* __restrict__ bias, float* __restrict__ C,
               int N, int Kd, float* sg)
{
    const int m0 = blockIdx.y * 128;
    const int n0 = blockIdx.x * 128;
    const int tid = threadIdx.x;
    const int wid = tid >> 5;
    const int wr = wid >> 2;     // 0..1 -> 64 rows
    const int wc = wid & 3;      // 0..3 -> 32 cols

    const int ar = tid >> 3, ac = (tid & 7) * 4;     // A: 128x32
    const int br = tid >> 5, bc = (tid & 31) * 4;    // B: 32x128

    wmma::fragment<wmma::accumulator, 16, 16, 8, float> acc[4][2];
#pragma unroll
    for (int i = 0; i < 4; i++)
#pragma unroll
        for (int j = 0; j < 2; j++) wmma::fill_fragment(acc[i][j], 0.f);

    const int nk = Kd >> 5;

    auto load_stage = [&](int s, int k0) {
        float* As = sg + s * GSTG;
        float* Bs = As + 4608;
#pragma unroll
        for (int it = 0; it < 4; it++)
            cpa16(&As[(ar + it * 32) * 36 + ac],
                  &A[(size_t)(m0 + ar + it * 32) * Kd + k0 + ac]);
#pragma unroll
        for (int it = 0; it < 4; it++)
            cpa16(&Bs[(br + it * 8) * 132 + bc],
                  &Bm[(size_t)(k0 + br + it * 8) * N + n0 + bc]);
    };

    load_stage(0, 0);  CPA_COMMIT();
    load_stage(1, 32); CPA_COMMIT();
    load_stage(2, 64); CPA_COMMIT();

    for (int c = 0; c < nk; c++) {
        int rem = nk - 1 - c;
        if (rem >= 2) { CPA_WAIT2(); } else if (rem == 1) { CPA_WAIT1(); } else { CPA_WAIT0(); }
        __syncthreads();
        float* As = sg + (c % 3) * GSTG;
        float* Bs = As + 4608;
#pragma unroll
        for (int kk = 0; kk < 4; kk++) {
            wmma::fragment<wmma::matrix_b, 16, 16, 8, wmma::precision::tf32, wmma::row_major> bf[2];
#pragma unroll
            for (int j = 0; j < 2; j++)
                wmma::load_matrix_sync(bf[j], &Bs[(kk * 8) * 132 + wc * 32 + j * 16], 132);
#pragma unroll
            for (int i = 0; i < 4; i++) {
                wmma::fragment<wmma::matrix_a, 16, 16, 8, wmma::precision::tf32, wmma::row_major> af;
                wmma::load_matrix_sync(af, &As[(wr * 64 + i * 16) * 36 + kk * 8], 36);
#pragma unroll
                for (int j = 0; j < 2; j++)
                    wmma::mma_sync(acc[i][j], af, bf[j], acc[i][j]);
            }
        }
        __syncthreads();
        if (c + 3 < nk) { load_stage(c % 3, (c + 3) * 32); CPA_COMMIT(); }
    }

    // epilogue in two 64-row halves staged through smem (stage-0 region)
    float* se = sg;   // 64 x 132
#pragma unroll
    for (int h = 0; h < 2; h++) {
        if (wr == h) {
#pragma unroll
            for (int i = 0; i < 4; i++)
#pragma unroll
                for (int j = 0; j < 2; j++)
                    wmma::store_matrix_sync(&se[(i * 16) * 132 + wc * 32 + j * 16],
                                            acc[i][j], 132, wmma::mem_row_major);
        }
        __syncthreads();
#pragma unroll
        for (int it = 0; it < 32; it++) {
            int lin = tid + it * 256;           // 0..8191 (64x128)
            int r = lin >> 7, cc = lin & 127;
            int row = m0 + h * 64 + r, col = n0 + cc;
            float cv = se[r * 132 + cc] + bias[col];
            if (EPI == 1) cv = fmaxf(cv, 0.f);
            if (EPI == 2) {
                int b_ = row >> 12, sgx = row & 4095;
                int w  = sgx >> 9,  sl = sgx & 511;
                int hh = col >> 8,  kd = col & 255;
                size_t idx = (((size_t)((b_ * NW + w) * HH + hh)) * WINS + sl) * KD + kd;
                C[idx] = cv;
            } else {
                C[(size_t)row * N + col] = cv;
            }
        }
        __syncthreads();
    }
}

template<int EPI>
__global__ __launch_bounds__(256, 2)
void gemm_tc(const float* __restrict__ A, const float* __restrict__ Bm,
             const float* __restrict__ bias, float* __restrict__ C,
             int N, int Kd)
{
    extern __shared__ float sg[];
    gemm_body<EPI>(A, Bm, bias, C, N, Kd, sg);
}

// fused QKV: grid.z selects {q,k,v}; one launch, better wave packing
__global__ __launch_bounds__(256, 2)
void qkv_tc(const float* __restrict__ x,
            const float* __restrict__ Wq, const float* __restrict__ Wk,
            const float* __restrict__ Wv,
            const float* __restrict__ bq, const float* __restrict__ bk,
            const float* __restrict__ bv)
{
    extern __shared__ float sg[];
    int z = blockIdx.z;
    const float* Bm  = (z == 0) ? Wq : (z == 1) ? Wk : Wv;
    const float* bia = (z == 0) ? bq : (z == 1) ? bk : bv;
    float* C = (z == 0) ? g_q : (z == 1) ? g_k : g_v;
    gemm_body<2>(x, Bm, bia, C, HH * KD, DD, sg);
}

// ---------------- windowed attention (tensor-core, 32-query tiles) ----------
// grid: (WIN/32 = 16, B*NW*H = 128), 256 threads (8 warps)
// smem: sS[32][516] | sK[512][20] | sQc[32][20]
// phase 2: per-warp double-buffered V tiles (8 warps x 2 x 16x36) alias sK.
#define SMEM_ATTN ((32*516 + 512*20 + 32*20) * 4)

__global__ __launch_bounds__(256, 2)
void attn_tc(const float* __restrict__ q, const float* __restrict__ k,
             const float* __restrict__ v, float* __restrict__ ctx)
{
    extern __shared__ float sm[];
    float* sS  = sm;                     // 32 x 516
    float* sK  = sm + 32 * 516;          // 512 x 20
    float* sQc = sK + 512 * 20;          // 32 x 20

    const int bwh = blockIdx.y;
    const int m0  = blockIdx.x * 32;
    const size_t base = (size_t)bwh * WINS * KD;
    const int tid = threadIdx.x;
    const int wid = tid >> 5;
    const int lane = tid & 31;

    // ---- phase 1: S = Q K^T / 16; warp tile 32 rows x 64 cols ----
    {
        wmma::fragment<wmma::accumulator, 16, 16, 8, float> acc[2][4];
#pragma unroll
        for (int i = 0; i < 2; i++)
#pragma unroll
            for (int j = 0; j < 4; j++) wmma::fill_fragment(acc[i][j], 0.f);

        for (int kc = 0; kc < 16; kc++) {           // 16-dim chunks of KD
            // Q chunk 32x16
            if (tid < 128) {
                int r = tid >> 2, c4 = (tid & 3) * 4;
                float4 f = *(const float4*)&q[base + (size_t)(m0 + r) * KD + kc * 16 + c4];
                *(float4*)&sQc[r * 20 + c4] = f;
            }
            // K chunk 512x16
#pragma unroll
            for (int it = 0; it < 8; it++) {
                int lin = tid + it * 256;
                int r = lin >> 2, c4 = (lin & 3) * 4;
                float4 f = *(const float4*)&k[base + (size_t)r * KD + kc * 16 + c4];
                *(float4*)&sK[r * 20 + c4] = f;
            }
            __syncthreads();
#pragma unroll
            for (int kk = 0; kk < 2; kk++) {
                wmma::fragment<wmma::matrix_a, 16, 16, 8, wmma::precision::tf32, wmma::row_major> af[2];
#pragma unroll
                for (int i = 0; i < 2; i++)
                    wmma::load_matrix_sync(af[i], &sQc[(i * 16) * 20 + kk * 8], 20);
#pragma unroll
                for (int j = 0; j < 4; j++) {
                    wmma::fragment<wmma::matrix_b, 16, 16, 8, wmma::precision::tf32, wmma::col_major> bf;
                    wmma::load_matrix_sync(bf, &sK[(wid * 64 + j * 16) * 20 + kk * 8], 20);
#pragma unroll
                    for (int i = 0; i < 2; i++)
                        wmma::mma_sync(acc[i][j], af[i], bf, acc[i][j]);
                }
            }
            __syncthreads();
        }
        // scale + dump to score strip
#pragma unroll
        for (int i = 0; i < 2; i++)
#pragma unroll
            for (int j = 0; j < 4; j++) {
#pragma unroll
                for (int t = 0; t < acc[i][j].num_elements; t++) acc[i][j].x[t] *= 0.0625f;
                wmma::store_matrix_sync(&sS[(i * 16) * 516 + wid * 64 + j * 16],
                                        acc[i][j], 516, wmma::mem_row_major);
            }
    }
    __syncthreads();

    // ---- softmax: 8 warps x 4 rows ----
#pragma unroll
    for (int rr = 0; rr < 4; rr++) {
        int r = wid * 4 + rr;
        float mx = -1e30f;
        for (int c = lane; c < 512; c += 32) mx = fmaxf(mx, sS[r * 516 + c]);
#pragma unroll
        for (int o = 16; o; o >>= 1) mx = fmaxf(mx, __shfl_xor_sync(0xffffffffu, mx, o));
        float sum = 0.f;
        for (int c = lane; c < 512; c += 32) {
            float e = expf(sS[r * 516 + c] - mx);
            sS[r * 516 + c] = e;
            sum += e;
        }
#pragma unroll
        for (int o = 16; o; o >>= 1) sum += __shfl_xor_sync(0xffffffffu, sum, o);
        float inv = 1.f / sum;
        for (int c = lane; c < 512; c += 32) sS[r * 516 + c] *= inv;
    }
    __syncthreads();   // scores final; sK region free for per-warp V tiles

    // ---- phase 2: ctx = P @ V; warp tile 32 rows x 32 cols ----
    // per-warp double-buffered V chunks (16 keys x 32 cols), cp.async
    {
        float* sVw = sK + wid * (2 * 576);   // 2 buffers of 16x36

        wmma::fragment<wmma::accumulator, 16, 16, 8, float> acc2[2][2];
#pragma unroll
        for (int i = 0; i < 2; i++)
#pragma unroll
            for (int j = 0; j < 2; j++) wmma::fill_fragment(acc2[i][j], 0.f);

        auto stage_v = [&](int kc) {
            float* dst = sVw + (kc & 1) * 576;
#pragma unroll
            for (int it = 0; it < 4; it++) {
                int lin = lane + it * 32;            // 0..127
                int r = lin >> 3, c4 = (lin & 7) * 4;
                cpa16(&dst[r * 36 + c4],
                      &v[base + (size_t)(kc * 16 + r) * KD + wid * 32 + c4]);
            }
        };

        stage_v(0); CPA_COMMIT();

        for (int kc = 0; kc < 32; kc++) {           // 16-key chunks
            if (kc + 1 < 32) { stage_v(kc + 1); CPA_COMMIT(); CPA_WAIT1(); }
            else             { CPA_WAIT0(); }
            __syncwarp();
            float* sVc = sVw + (kc & 1) * 576;
#pragma unroll
            for (int kk = 0; kk < 2; kk++) {
                wmma::fragment<wmma::matrix_a, 16, 16, 8, wmma::precision::tf32, wmma::row_major> af[2];
#pragma unroll
                for (int i = 0; i < 2; i++)
                    wmma::load_matrix_sync(af[i], &sS[(i * 16) * 516 + kc * 16 + kk * 8], 516);
#pragma unroll
                for (int j = 0; j < 2; j++) {
                    wmma::fragment<wmma::matrix_b, 16, 16, 8, wmma::precision::tf32, wmma::row_major> bf;
                    wmma::load_matrix_sync(bf, &sVc[(kk * 8) * 36 + j * 16], 36);
#pragma unroll
                    for (int i = 0; i < 2; i++)
                        wmma::mma_sync(acc2[i][j], af[i], bf, acc2[i][j]);
                }
            }
            __syncwarp();   // protect buffer being overwritten next iteration
        }

        // write ctx: token-major [M, H*K]
        const int b_ = bwh >> 4, w = (bwh >> 1) & 7, h = bwh & 1;
        const size_t tok0 = (size_t)b_ * SS + w * WINS + m0;
#pragma unroll
        for (int i = 0; i < 2; i++)
#pragma unroll
            for (int j = 0; j < 2; j++) {
                size_t row = tok0 + i * 16;
                int col = h * KD + wid * 32 + j * 16;
                wmma::store_matrix_sync(&ctx[row * (HH * KD) + col], acc2[i][j],
                                        HH * KD, wmma::mem_row_major);
            }
    }
}

// ---------------- residual + LayerNorm -------------------------------------
__global__ __launch_bounds__(256)
void ln_k(const float* __restrict__ a, const float* __restrict__ r,
          const float* __restrict__ g, const float* __restrict__ bta,
          float* __restrict__ out)
{
    int wid = threadIdx.x >> 5, lane = threadIdx.x & 31;
    size_t row = (size_t)blockIdx.x * 8 + wid;
    const float* pa = a + row * DD;
    const float* pr = r + row * DD;
    float v[8];
    float s = 0.f;
#pragma unroll
    for (int j = 0; j < 8; j++) {
        int c = lane + j * 32;
        v[j] = pa[c] + pr[c];
        s += v[j];
    }
#pragma unroll
    for (int o = 16; o; o >>= 1) s += __shfl_xor_sync(0xffffffffu, s, o);
    float mu = s * (1.f / 256.f);
    float vs = 0.f;
#pragma unroll
    for (int j = 0; j < 8; j++) {
        float d = v[j] - mu;
        vs += d * d;
    }
#pragma unroll
    for (int o = 16; o; o >>= 1) vs += __shfl_xor_sync(0xffffffffu, vs, o);
    float inv = rsqrtf(vs * (1.f / 256.f) + 1e-3f);
#pragma unroll
    for (int j = 0; j < 8; j++) {
        int c = lane + j * 32;
        out[row * DD + c] = (v[j] - mu) * inv * g[c] + bta[c];
    }
}

// ---------------- launch ----------------------------------------------------
extern "C" void kernel_launch(void* const* d_in, const int* in_sizes, int n_in,
                              void* d_out, int out_size)
{
    const float* x    = (const float*)d_in[0];
    const float* Wq   = (const float*)d_in[1];
    const float* bq   = (const float*)d_in[2];
    const float* Wk   = (const float*)d_in[3];
    const float* bk   = (const float*)d_in[4];
    const float* Wv   = (const float*)d_in[5];
    const float* bv   = (const float*)d_in[6];
    const float* Wo   = (const float*)d_in[7];
    const float* bo   = (const float*)d_in[8];
    const float* ln1g = (const float*)d_in[9];
    const float* ln1b = (const float*)d_in[10];
    const float* W1   = (const float*)d_in[11];
    const float* b1   = (const float*)d_in[12];
    const float* W2   = (const float*)d_in[13];
    const float* b2   = (const float*)d_in[14];
    const float* ln2g = (const float*)d_in[15];
    const float* ln2b = (const float*)d_in[16];

    float *q, *k, *v, *ctx, *y, *t, *hbuf;
    cudaGetSymbolAddress((void**)&q,    g_q);
    cudaGetSymbolAddress((void**)&k,    g_k);
    cudaGetSymbolAddress((void**)&v,    g_v);
    cudaGetSymbolAddress((void**)&ctx,  g_ctx);
    cudaGetSymbolAddress((void**)&y,    g_y);
    cudaGetSymbolAddress((void**)&t,    g_t);
    cudaGetSymbolAddress((void**)&hbuf, g_h);

    cudaFuncSetAttribute(attn_tc, cudaFuncAttributeMaxDynamicSharedMemorySize, SMEM_ATTN);
    cudaFuncSetAttribute(qkv_tc,     cudaFuncAttributeMaxDynamicSharedMemorySize, GEMM_SMEM);
    cudaFuncSetAttribute(gemm_tc<0>, cudaFuncAttributeMaxDynamicSharedMemorySize, GEMM_SMEM);
    cudaFuncSetAttribute(gemm_tc<1>, cudaFuncAttributeMaxDynamicSharedMemorySize, GEMM_SMEM);

    dim3 blk(256);

    // fused QKV projections (scatter into [b,w,h,s,k])
    qkv_tc<<<dim3(4, 256, 3), blk, GEMM_SMEM>>>(x, Wq, Wk, Wv, bq, bk, bv);

    // windowed attention
    attn_tc<<<dim3(16, 128), blk, SMEM_ATTN>>>(q, k, v, ctx);

    // output projection + LN1
    gemm_tc<0><<<dim3(2, 256), blk, GEMM_SMEM>>>(ctx, Wo, bo, t, DD, HH * KD);
    ln_k<<<MTOK / 8, blk>>>(t, x, ln1g, ln1b, y);

    // FFN
    gemm_tc<1><<<dim3(8, 256), blk, GEMM_SMEM>>>(y, W1, b1, hbuf, DFF, DD);
    gemm_tc<0><<<dim3(2, 256), blk, GEMM_SMEM>>>(hbuf, W2, b2, t, DD, DFF);
    ln_k<<<MTOK / 8, blk>>>(t, y, ln2g, ln2b, (float*)d_out);
}

// round 12
// speedup vs baseline: 2.9415x; 1.0479x over previous
#include <cuda_runtime.h>
#include <cstdint>
#include <mma.h>
using namespace nvcuda;

// Problem constants
#define BB   8
#define SS   4096
#define DD   256
#define NW   8
#define WINS 512
#define HH   2
#define KD   256
#define DFF  1024
#define MTOK (BB*SS)          // 32768 tokens

// ---------------- device scratch (static allocation; no cudaMalloc) -------
__device__ float g_q  [(size_t)BB*SS*HH*KD];   // [b,w,h,s,k]
__device__ float g_k  [(size_t)BB*SS*HH*KD];
__device__ float g_v  [(size_t)BB*SS*HH*KD];
__device__ float g_ctx[(size_t)BB*SS*HH*KD];   // [token, h*K+k]
__device__ float g_y  [(size_t)MTOK*DD];       // post-LN1
__device__ float g_t  [(size_t)MTOK*DD];       // pre-LN scratch
__device__ float g_h  [(size_t)MTOK*DFF];      // FFN hidden

// ---------------- cp.async helpers -----------------------------------------
__device__ __forceinline__ void cpa16(float* smem, const float* g) {
    unsigned s = (unsigned)__cvta_generic_to_shared(smem);
    asm volatile("cp.async.cg.shared.global [%0], [%1], 16;" :: "r"(s), "l"(g));
}
#define CPA_COMMIT() asm volatile("cp.async.commit_group;")
#define CPA_WAIT2()  asm volatile("cp.async.wait_group 2;")
#define CPA_WAIT1()  asm volatile("cp.async.wait_group 1;")
#define CPA_WAIT0()  asm volatile("cp.async.wait_group 0;")

// ---------------- tf32 wmma GEMM: block 128x256, warp tile 64x64 ------------
// C[M,N] = A[M,Kd] @ B[Kd,N] + bias[N]; EPI: 0 plain, 1 relu, 2 qkv-scatter
// 8 warps in 2x4 grid; 3-stage cp.async; 1 CTA/SM (155KB smem).
#define GSTG  12928                   // floats/stage: A 128*36 + B 32*260
#define GEMM_SMEM (3*GSTG*4)          // 155,136 B

template<int EPI>
__device__ __forceinline__
void gemm_body(const float* __restrict__ A, const float* __restrict__ Bm,
               const float* __restrict__ bias, float* __restrict__ C,
               int N, int Kd, float* sg)
{
    const int m0 = blockIdx.y * 128;
    const int n0 = blockIdx.x * 256;
    const int tid = threadIdx.x;
    const int wid = tid >> 5;
    const int wr = wid >> 2;     // 0..1 -> 64-row group
    const int wc = wid & 3;      // 0..3 -> 64-col group

    const int ar = tid >> 3, ac = (tid & 7) * 4;     // A: 128x32, 4 float4/thr

    wmma::fragment<wmma::accumulator, 16, 16, 8, float> acc[4][4];
#pragma unroll
    for (int i = 0; i < 4; i++)
#pragma unroll
        for (int j = 0; j < 4; j++) wmma::fill_fragment(acc[i][j], 0.f);

    const int nk = Kd >> 5;

    auto load_stage = [&](int s, int k0) {
        float* As = sg + s * GSTG;
        float* Bs = As + 4608;
#pragma unroll
        for (int it = 0; it < 4; it++)
            cpa16(&As[(ar + it * 32) * 36 + ac],
                  &A[(size_t)(m0 + ar + it * 32) * Kd + k0 + ac]);
#pragma unroll
        for (int it = 0; it < 8; it++) {             // B: 32x256, 8 float4/thr
            int lin = tid + it * 256;
            int r = lin >> 6, c = (lin & 63) * 4;
            cpa16(&Bs[r * 260 + c],
                  &Bm[(size_t)(k0 + r) * N + n0 + c]);
        }
    };

    load_stage(0, 0);  CPA_COMMIT();
    load_stage(1, 32); CPA_COMMIT();
    load_stage(2, 64); CPA_COMMIT();

    for (int c = 0; c < nk; c++) {
        int rem = nk - 1 - c;
        if (rem >= 2) { CPA_WAIT2(); } else if (rem == 1) { CPA_WAIT1(); } else { CPA_WAIT0(); }
        __syncthreads();
        float* As = sg + (c % 3) * GSTG;
        float* Bs = As + 4608;
#pragma unroll
        for (int kk = 0; kk < 4; kk++) {
            wmma::fragment<wmma::matrix_a, 16, 16, 8, wmma::precision::tf32, wmma::row_major> af[4];
#pragma unroll
            for (int i = 0; i < 4; i++)
                wmma::load_matrix_sync(af[i], &As[(wr * 64 + i * 16) * 36 + kk * 8], 36);
#pragma unroll
            for (int j = 0; j < 4; j++) {
                wmma::fragment<wmma::matrix_b, 16, 16, 8, wmma::precision::tf32, wmma::row_major> bf;
                wmma::load_matrix_sync(bf, &Bs[(kk * 8) * 260 + wc * 64 + j * 16], 260);
#pragma unroll
                for (int i = 0; i < 4; i++)
                    wmma::mma_sync(acc[i][j], af[i], bf, acc[i][j]);
            }
        }
        __syncthreads();
        if (c + 3 < nk) { load_stage(c % 3, (c + 3) * 32); CPA_COMMIT(); }
    }

    // epilogue: two 64-row halves staged through smem (64 x 264)
    float* se = sg;
#pragma unroll
    for (int h = 0; h < 2; h++) {
        if (wr == h) {
#pragma unroll
            for (int i = 0; i < 4; i++)
#pragma unroll
                for (int j = 0; j < 4; j++)
                    wmma::store_matrix_sync(&se[(i * 16) * 264 + wc * 64 + j * 16],
                                            acc[i][j], 264, wmma::mem_row_major);
        }
        __syncthreads();
#pragma unroll
        for (int it = 0; it < 16; it++) {
            int lin = tid + it * 256;           // 0..4095 quads (64x256 elems)
            int r = lin >> 6, c4 = (lin & 63) * 4;
            int row = m0 + h * 64 + r, col = n0 + c4;
            float4 cv;
            cv.x = se[r * 264 + c4 + 0] + bias[col + 0];
            cv.y = se[r * 264 + c4 + 1] + bias[col + 1];
            cv.z = se[r * 264 + c4 + 2] + bias[col + 2];
            cv.w = se[r * 264 + c4 + 3] + bias[col + 3];
            if (EPI == 1) {
                cv.x = fmaxf(cv.x, 0.f); cv.y = fmaxf(cv.y, 0.f);
                cv.z = fmaxf(cv.z, 0.f); cv.w = fmaxf(cv.w, 0.f);
            }
            if (EPI == 2) {
                int b_ = row >> 12, sgx = row & 4095;
                int w  = sgx >> 9,  sl = sgx & 511;
                int hh = col >> 8,  kd = col & 255;
                size_t idx = (((size_t)((b_ * NW + w) * HH + hh)) * WINS + sl) * KD + kd;
                *(float4*)&C[idx] = cv;
            } else {
                *(float4*)&C[(size_t)row * N + col] = cv;
            }
        }
        __syncthreads();
    }
}

template<int EPI>
__global__ __launch_bounds__(256, 1)
void gemm_tc(const float* __restrict__ A, const float* __restrict__ Bm,
             const float* __restrict__ bias, float* __restrict__ C,
             int N, int Kd)
{
    extern __shared__ float sg[];
    gemm_body<EPI>(A, Bm, bias, C, N, Kd, sg);
}

// fused QKV: grid.z selects {q,k,v}
__global__ __launch_bounds__(256, 1)
void qkv_tc(const float* __restrict__ x,
            const float* __restrict__ Wq, const float* __restrict__ Wk,
            const float* __restrict__ Wv,
            const float* __restrict__ bq, const float* __restrict__ bk,
            const float* __restrict__ bv)
{
    extern __shared__ float sg[];
    int z = blockIdx.z;
    const float* Bm  = (z == 0) ? Wq : (z == 1) ? Wk : Wv;
    const float* bia = (z == 0) ? bq : (z == 1) ? bk : bv;
    float* C = (z == 0) ? g_q : (z == 1) ? g_k : g_v;
    gemm_body<2>(x, Bm, bia, C, HH * KD, DD, sg);
}

// ---------------- windowed attention (tensor-core, 32-query tiles) ----------
// grid: (WIN/32 = 16, B*NW*H = 128), 256 threads (8 warps)
// smem: sS[32][516] | sK[512][20] | sQc[32][20]
// phase 2: per-warp double-buffered V tiles (8 warps x 2 x 16x36) alias sK.
#define SMEM_ATTN ((32*516 + 512*20 + 32*20) * 4)

__global__ __launch_bounds__(256, 2)
void attn_tc(const float* __restrict__ q, const float* __restrict__ k,
             const float* __restrict__ v, float* __restrict__ ctx)
{
    extern __shared__ float sm[];
    float* sS  = sm;                     // 32 x 516
    float* sK  = sm + 32 * 516;          // 512 x 20
    float* sQc = sK + 512 * 20;          // 32 x 20

    const int bwh = blockIdx.y;
    const int m0  = blockIdx.x * 32;
    const size_t base = (size_t)bwh * WINS * KD;
    const int tid = threadIdx.x;
    const int wid = tid >> 5;
    const int lane = tid & 31;

    // ---- phase 1: S = Q K^T / 16; warp tile 32 rows x 64 cols ----
    {
        wmma::fragment<wmma::accumulator, 16, 16, 8, float> acc[2][4];
#pragma unroll
        for (int i = 0; i < 2; i++)
#pragma unroll
            for (int j = 0; j < 4; j++) wmma::fill_fragment(acc[i][j], 0.f);

        for (int kc = 0; kc < 16; kc++) {           // 16-dim chunks of KD
            if (tid < 128) {
                int r = tid >> 2, c4 = (tid & 3) * 4;
                float4 f = *(const float4*)&q[base + (size_t)(m0 + r) * KD + kc * 16 + c4];
                *(float4*)&sQc[r * 20 + c4] = f;
            }
#pragma unroll
            for (int it = 0; it < 8; it++) {
                int lin = tid + it * 256;
                int r = lin >> 2, c4 = (lin & 3) * 4;
                float4 f = *(const float4*)&k[base + (size_t)r * KD + kc * 16 + c4];
                *(float4*)&sK[r * 20 + c4] = f;
            }
            __syncthreads();
#pragma unroll
            for (int kk = 0; kk < 2; kk++) {
                wmma::fragment<wmma::matrix_a, 16, 16, 8, wmma::precision::tf32, wmma::row_major> af[2];
#pragma unroll
                for (int i = 0; i < 2; i++)
                    wmma::load_matrix_sync(af[i], &sQc[(i * 16) * 20 + kk * 8], 20);
#pragma unroll
                for (int j = 0; j < 4; j++) {
                    wmma::fragment<wmma::matrix_b, 16, 16, 8, wmma::precision::tf32, wmma::col_major> bf;
                    wmma::load_matrix_sync(bf, &sK[(wid * 64 + j * 16) * 20 + kk * 8], 20);
#pragma unroll
                    for (int i = 0; i < 2; i++)
                        wmma::mma_sync(acc[i][j], af[i], bf, acc[i][j]);
                }
            }
            __syncthreads();
        }
#pragma unroll
        for (int i = 0; i < 2; i++)
#pragma unroll
            for (int j = 0; j < 4; j++) {
#pragma unroll
                for (int t = 0; t < acc[i][j].num_elements; t++) acc[i][j].x[t] *= 0.0625f;
                wmma::store_matrix_sync(&sS[(i * 16) * 516 + wid * 64 + j * 16],
                                        acc[i][j], 516, wmma::mem_row_major);
            }
    }
    __syncthreads();

    // ---- softmax: 8 warps x 4 rows ----
#pragma unroll
    for (int rr = 0; rr < 4; rr++) {
        int r = wid * 4 + rr;
        float mx = -1e30f;
        for (int c = lane; c < 512; c += 32) mx = fmaxf(mx, sS[r * 516 + c]);
#pragma unroll
        for (int o = 16; o; o >>= 1) mx = fmaxf(mx, __shfl_xor_sync(0xffffffffu, mx, o));
        float sum = 0.f;
        for (int c = lane; c < 512; c += 32) {
            float e = expf(sS[r * 516 + c] - mx);
            sS[r * 516 + c] = e;
            sum += e;
        }
#pragma unroll
        for (int o = 16; o; o >>= 1) sum += __shfl_xor_sync(0xffffffffu, sum, o);
        float inv = 1.f / sum;
        for (int c = lane; c < 512; c += 32) sS[r * 516 + c] *= inv;
    }
    __syncthreads();   // scores final; sK region free for per-warp V tiles

    // ---- phase 2: ctx = P @ V; warp tile 32 rows x 32 cols ----
    {
        float* sVw = sK + wid * (2 * 576);   // 2 buffers of 16x36

        wmma::fragment<wmma::accumulator, 16, 16, 8, float> acc2[2][2];
#pragma unroll
        for (int i = 0; i < 2; i++)
#pragma unroll
            for (int j = 0; j < 2; j++) wmma::fill_fragment(acc2[i][j], 0.f);

        auto stage_v = [&](int kc) {
            float* dst = sVw + (kc & 1) * 576;
#pragma unroll
            for (int it = 0; it < 4; it++) {
                int lin = lane + it * 32;
                int r = lin >> 3, c4 = (lin & 7) * 4;
                cpa16(&dst[r * 36 + c4],
                      &v[base + (size_t)(kc * 16 + r) * KD + wid * 32 + c4]);
            }
        };

        stage_v(0); CPA_COMMIT();

        for (int kc = 0; kc < 32; kc++) {
            if (kc + 1 < 32) { stage_v(kc + 1); CPA_COMMIT(); CPA_WAIT1(); }
            else             { CPA_WAIT0(); }
            __syncwarp();
            float* sVc = sVw + (kc & 1) * 576;
#pragma unroll
            for (int kk = 0; kk < 2; kk++) {
                wmma::fragment<wmma::matrix_a, 16, 16, 8, wmma::precision::tf32, wmma::row_major> af[2];
#pragma unroll
                for (int i = 0; i < 2; i++)
                    wmma::load_matrix_sync(af[i], &sS[(i * 16) * 516 + kc * 16 + kk * 8], 516);
#pragma unroll
                for (int j = 0; j < 2; j++) {
                    wmma::fragment<wmma::matrix_b, 16, 16, 8, wmma::precision::tf32, wmma::row_major> bf;
                    wmma::load_matrix_sync(bf, &sVc[(kk * 8) * 36 + j * 16], 36);
#pragma unroll
                    for (int i = 0; i < 2; i++)
                        wmma::mma_sync(acc2[i][j], af[i], bf, acc2[i][j]);
                }
            }
            __syncwarp();
        }

        const int b_ = bwh >> 4, w = (bwh >> 1) & 7, h = bwh & 1;
        const size_t tok0 = (size_t)b_ * SS + w * WINS + m0;
#pragma unroll
        for (int i = 0; i < 2; i++)
#pragma unroll
            for (int j = 0; j < 2; j++) {
                size_t row = tok0 + i * 16;
                int col = h * KD + wid * 32 + j * 16;
                wmma::store_matrix_sync(&ctx[row * (HH * KD) + col], acc2[i][j],
                                        HH * KD, wmma::mem_row_major);
            }
    }
}

// ---------------- residual + LayerNorm -------------------------------------
__global__ __launch_bounds__(256)
void ln_k(const float* __restrict__ a, const float* __restrict__ r,
          const float* __restrict__ g, const float* __restrict__ bta,
          float* __restrict__ out)
{
    int wid = threadIdx.x >> 5, lane = threadIdx.x & 31;
    size_t row = (size_t)blockIdx.x * 8 + wid;
    const float* pa = a + row * DD;
    const float* pr = r + row * DD;
    float v[8];
    float s = 0.f;
#pragma unroll
    for (int j = 0; j < 8; j++) {
        int c = lane + j * 32;
        v[j] = pa[c] + pr[c];
        s += v[j];
    }
#pragma unroll
    for (int o = 16; o; o >>= 1) s += __shfl_xor_sync(0xffffffffu, s, o);
    float mu = s * (1.f / 256.f);
    float vs = 0.f;
#pragma unroll
    for (int j = 0; j < 8; j++) {
        float d = v[j] - mu;
        vs += d * d;
    }
#pragma unroll
    for (int o = 16; o; o >>= 1) vs += __shfl_xor_sync(0xffffffffu, vs, o);
    float inv = rsqrtf(vs * (1.f / 256.f) + 1e-3f);
#pragma unroll
    for (int j = 0; j < 8; j++) {
        int c = lane + j * 32;
        out[row * DD + c] = (v[j] - mu) * inv * g[c] + bta[c];
    }
}

// ---------------- launch ----------------------------------------------------
extern "C" void kernel_launch(void* const* d_in, const int* in_sizes, int n_in,
                              void* d_out, int out_size)
{
    const float* x    = (const float*)d_in[0];
    const float* Wq   = (const float*)d_in[1];
    const float* bq   = (const float*)d_in[2];
    const float* Wk   = (const float*)d_in[3];
    const float* bk   = (const float*)d_in[4];
    const float* Wv   = (const float*)d_in[5];
    const float* bv   = (const float*)d_in[6];
    const float* Wo   = (const float*)d_in[7];
    const float* bo   = (const float*)d_in[8];
    const float* ln1g = (const float*)d_in[9];
    const float* ln1b = (const float*)d_in[10];
    const float* W1   = (const float*)d_in[11];
    const float* b1   = (const float*)d_in[12];
    const float* W2   = (const float*)d_in[13];
    const float* b2   = (const float*)d_in[14];
    const float* ln2g = (const float*)d_in[15];
    const float* ln2b = (const float*)d_in[16];

    float *q, *k, *v, *ctx, *y, *t, *hbuf;
    cudaGetSymbolAddress((void**)&q,    g_q);
    cudaGetSymbolAddress((void**)&k,    g_k);
    cudaGetSymbolAddress((void**)&v,    g_v);
    cudaGetSymbolAddress((void**)&ctx,  g_ctx);
    cudaGetSymbolAddress((void**)&y,    g_y);
    cudaGetSymbolAddress((void**)&t,    g_t);
    cudaGetSymbolAddress((void**)&hbuf, g_h);

    cudaFuncSetAttribute(attn_tc,    cudaFuncAttributeMaxDynamicSharedMemorySize, SMEM_ATTN);
    cudaFuncSetAttribute(qkv_tc,     cudaFuncAttributeMaxDynamicSharedMemorySize, GEMM_SMEM);
    cudaFuncSetAttribute(gemm_tc<0>, cudaFuncAttributeMaxDynamicSharedMemorySize, GEMM_SMEM);
    cudaFuncSetAttribute(gemm_tc<1>, cudaFuncAttributeMaxDynamicSharedMemorySize, GEMM_SMEM);

    dim3 blk(256);

    // fused QKV projections (scatter into [b,w,h,s,k]); N=512 -> 2 n-tiles
    qkv_tc<<<dim3(2, 256, 3), blk, GEMM_SMEM>>>(x, Wq, Wk, Wv, bq, bk, bv);

    // windowed attention
    attn_tc<<<dim3(16, 128), blk, SMEM_ATTN>>>(q, k, v, ctx);

    // output projection + LN1 (N=256 -> 1 n-tile)
    gemm_tc<0><<<dim3(1, 256), blk, GEMM_SMEM>>>(ctx, Wo, bo, t, DD, HH * KD);
    ln_k<<<MTOK / 8, blk>>>(t, x, ln1g, ln1b, y);

    // FFN
    gemm_tc<1><<<dim3(4, 256), blk, GEMM_SMEM>>>(y, W1, b1, hbuf, DFF, DD);
    gemm_tc<0><<<dim3(1, 256), blk, GEMM_SMEM>>>(hbuf, W2, b2, t, DD, DFF);
    ln_k<<<MTOK / 8, blk>>>(t, y, ln2g, ln2b, (float*)d_out);
}

// round 13
// speedup vs baseline: 2.9641x; 1.0077x over previous
#include <cuda_runtime.h>
#include <cstdint>
#include <mma.h>
using namespace nvcuda;

// Problem constants
#define BB   8
#define SS   4096
#define DD   256
#define NW   8
#define WINS 512
#define HH   2
#define KD   256
#define DFF  1024
#define MTOK (BB*SS)          // 32768 tokens

// ---------------- device scratch (static allocation; no cudaMalloc) -------
__device__ float g_q  [(size_t)BB*SS*HH*KD];   // [b,w,h,s,k]
__device__ float g_k  [(size_t)BB*SS*HH*KD];
__device__ float g_v  [(size_t)BB*SS*HH*KD];
__device__ float g_ctx[(size_t)BB*SS*HH*KD];   // [token, h*K+k]
__device__ float g_y  [(size_t)MTOK*DD];       // post-LN1
__device__ float g_h  [(size_t)MTOK*DFF];      // FFN hidden

// ---------------- cp.async helpers -----------------------------------------
__device__ __forceinline__ void cpa16(float* smem, const float* g) {
    unsigned s = (unsigned)__cvta_generic_to_shared(smem);
    asm volatile("cp.async.cg.shared.global [%0], [%1], 16;" :: "r"(s), "l"(g));
}
#define CPA_COMMIT() asm volatile("cp.async.commit_group;")
#define CPA_WAIT2()  asm volatile("cp.async.wait_group 2;")
#define CPA_WAIT1()  asm volatile("cp.async.wait_group 1;")
#define CPA_WAIT0()  asm volatile("cp.async.wait_group 0;")

// ---------------- tf32 wmma GEMM: block 128x256, warp tile 64x64 ------------
// C[M,N] = A[M,Kd] @ B[Kd,N] + bias[N]
// EPI: 0 plain, 1 relu, 2 qkv-scatter, 3 residual+LayerNorm (needs N==256)
// 8 warps in 2x4 grid; 3-stage cp.async; 1 CTA/SM (155KB smem).
#define GSTG  12928                   // floats/stage: A 128*36 + B 32*260
#define GEMM_SMEM (3*GSTG*4)          // 155,136 B

template<int EPI>
__device__ __forceinline__
void gemm_body(const float* __restrict__ A, const float* __restrict__ Bm,
               const float* __restrict__ bias, float* __restrict__ C,
               int N, int Kd, float* sg,
               const float* __restrict__ resid,
               const float* __restrict__ lng,
               const float* __restrict__ lnb)
{
    const int m0 = blockIdx.y * 128;
    const int n0 = blockIdx.x * 256;
    const int tid = threadIdx.x;
    const int wid = tid >> 5;
    const int lane = tid & 31;
    const int wr = wid >> 2;     // 0..1 -> 64-row group
    const int wc = wid & 3;      // 0..3 -> 64-col group

    const int ar = tid >> 3, ac = (tid & 7) * 4;     // A: 128x32, 4 float4/thr

    wmma::fragment<wmma::accumulator, 16, 16, 8, float> acc[4][4];
#pragma unroll
    for (int i = 0; i < 4; i++)
#pragma unroll
        for (int j = 0; j < 4; j++) wmma::fill_fragment(acc[i][j], 0.f);

    const int nk = Kd >> 5;

    auto load_stage = [&](int s, int k0) {
        float* As = sg + s * GSTG;
        float* Bs = As + 4608;
#pragma unroll
        for (int it = 0; it < 4; it++)
            cpa16(&As[(ar + it * 32) * 36 + ac],
                  &A[(size_t)(m0 + ar + it * 32) * Kd + k0 + ac]);
#pragma unroll
        for (int it = 0; it < 8; it++) {             // B: 32x256, 8 float4/thr
            int lin = tid + it * 256;
            int r = lin >> 6, c = (lin & 63) * 4;
            cpa16(&Bs[r * 260 + c],
                  &Bm[(size_t)(k0 + r) * N + n0 + c]);
        }
    };

    load_stage(0, 0);  CPA_COMMIT();
    load_stage(1, 32); CPA_COMMIT();
    load_stage(2, 64); CPA_COMMIT();

    for (int c = 0; c < nk; c++) {
        int rem = nk - 1 - c;
        if (rem >= 2) { CPA_WAIT2(); } else if (rem == 1) { CPA_WAIT1(); } else { CPA_WAIT0(); }
        __syncthreads();
        float* As = sg + (c % 3) * GSTG;
        float* Bs = As + 4608;
#pragma unroll
        for (int kk = 0; kk < 4; kk++) {
            wmma::fragment<wmma::matrix_a, 16, 16, 8, wmma::precision::tf32, wmma::row_major> af[4];
#pragma unroll
            for (int i = 0; i < 4; i++)
                wmma::load_matrix_sync(af[i], &As[(wr * 64 + i * 16) * 36 + kk * 8], 36);
#pragma unroll
            for (int j = 0; j < 4; j++) {
                wmma::fragment<wmma::matrix_b, 16, 16, 8, wmma::precision::tf32, wmma::row_major> bf;
                wmma::load_matrix_sync(bf, &Bs[(kk * 8) * 260 + wc * 64 + j * 16], 260);
#pragma unroll
                for (int i = 0; i < 4; i++)
                    wmma::mma_sync(acc[i][j], af[i], bf, acc[i][j]);
            }
        }
        __syncthreads();
        if (c + 3 < nk) { load_stage(c % 3, (c + 3) * 32); CPA_COMMIT(); }
    }

    // epilogue: two 64-row halves staged through smem (64 x 264)
    float* se = sg;
#pragma unroll
    for (int h = 0; h < 2; h++) {
        if (wr == h) {
#pragma unroll
            for (int i = 0; i < 4; i++)
#pragma unroll
                for (int j = 0; j < 4; j++)
                    wmma::store_matrix_sync(&se[(i * 16) * 264 + wc * 64 + j * 16],
                                            acc[i][j], 264, wmma::mem_row_major);
        }
        __syncthreads();
        if (EPI == 3) {
            // residual + LayerNorm over full 256-wide rows; warp w -> rows w*8..w*8+7
#pragma unroll
            for (int rr = 0; rr < 8; rr++) {
                int r = wid * 8 + rr;                // 0..63 within half
                size_t row = (size_t)(m0 + h * 64 + r);
                float vv[8];
                float s = 0.f;
#pragma unroll
                for (int j = 0; j < 8; j++) {
                    int cc = lane + j * 32;
                    vv[j] = se[r * 264 + cc] + bias[cc] + resid[row * DD + cc];
                    s += vv[j];
                }
#pragma unroll
                for (int o = 16; o; o >>= 1) s += __shfl_xor_sync(0xffffffffu, s, o);
                float mu = s * (1.f / 256.f);
                float vs = 0.f;
#pragma unroll
                for (int j = 0; j < 8; j++) {
                    float d = vv[j] - mu;
                    vs += d * d;
                }
#pragma unroll
                for (int o = 16; o; o >>= 1) vs += __shfl_xor_sync(0xffffffffu, vs, o);
                float inv = rsqrtf(vs * (1.f / 256.f) + 1e-3f);
#pragma unroll
                for (int j = 0; j < 8; j++) {
                    int cc = lane + j * 32;
                    C[row * DD + cc] = (vv[j] - mu) * inv * lng[cc] + lnb[cc];
                }
            }
        } else {
#pragma unroll
            for (int it = 0; it < 16; it++) {
                int lin = tid + it * 256;           // 0..4095 quads (64x256 elems)
                int r = lin >> 6, c4 = (lin & 63) * 4;
                int row = m0 + h * 64 + r, col = n0 + c4;
                float4 cv;
                cv.x = se[r * 264 + c4 + 0] + bias[col + 0];
                cv.y = se[r * 264 + c4 + 1] + bias[col + 1];
                cv.z = se[r * 264 + c4 + 2] + bias[col + 2];
                cv.w = se[r * 264 + c4 + 3] + bias[col + 3];
                if (EPI == 1) {
                    cv.x = fmaxf(cv.x, 0.f); cv.y = fmaxf(cv.y, 0.f);
                    cv.z = fmaxf(cv.z, 0.f); cv.w = fmaxf(cv.w, 0.f);
                }
                if (EPI == 2) {
                    int b_ = row >> 12, sgx = row & 4095;
                    int w  = sgx >> 9,  sl = sgx & 511;
                    int hh = col >> 8,  kd = col & 255;
                    size_t idx = (((size_t)((b_ * NW + w) * HH + hh)) * WINS + sl) * KD + kd;
                    *(float4*)&C[idx] = cv;
                } else {
                    *(float4*)&C[(size_t)row * N + col] = cv;
                }
            }
        }
        __syncthreads();
    }
}

template<int EPI>
__global__ __launch_bounds__(256, 1)
void gemm_tc(const float* __restrict__ A, const float* __restrict__ Bm,
             const float* __restrict__ bias, float* __restrict__ C,
             int N, int Kd,
             const float* resid, const float* lng, const float* lnb)
{
    extern __shared__ float sg[];
    gemm_body<EPI>(A, Bm, bias, C, N, Kd, sg, resid, lng, lnb);
}

// fused QKV: grid.z selects {q,k,v}
__global__ __launch_bounds__(256, 1)
void qkv_tc(const float* __restrict__ x,
            const float* __restrict__ Wq, const float* __restrict__ Wk,
            const float* __restrict__ Wv,
            const float* __restrict__ bq, const float* __restrict__ bk,
            const float* __restrict__ bv)
{
    extern __shared__ float sg[];
    int z = blockIdx.z;
    const float* Bm  = (z == 0) ? Wq : (z == 1) ? Wk : Wv;
    const float* bia = (z == 0) ? bq : (z == 1) ? bk : bv;
    float* C = (z == 0) ? g_q : (z == 1) ? g_k : g_v;
    gemm_body<2>(x, Bm, bia, C, HH * KD, DD, sg, nullptr, nullptr, nullptr);
}

// ---------------- windowed attention (tensor-core, 32-query tiles) ----------
// grid: (WIN/32 = 16, B*NW*H = 128), 256 threads (8 warps)
// smem: sS[32][516] | sK[512][20] | sQc[32][20]
// phase 2: per-warp double-buffered V tiles (8 warps x 2 x 16x36) alias sK.
#define SMEM_ATTN ((32*516 + 512*20 + 32*20) * 4)

__global__ __launch_bounds__(256, 2)
void attn_tc(const float* __restrict__ q, const float* __restrict__ k,
             const float* __restrict__ v, float* __restrict__ ctx)
{
    extern __shared__ float sm[];
    float* sS  = sm;                     // 32 x 516
    float* sK  = sm + 32 * 516;          // 512 x 20
    float* sQc = sK + 512 * 20;          // 32 x 20

    const int bwh = blockIdx.y;
    const int m0  = blockIdx.x * 32;
    const size_t base = (size_t)bwh * WINS * KD;
    const int tid = threadIdx.x;
    const int wid = tid >> 5;
    const int lane = tid & 31;

    // ---- phase 1: S = Q K^T / 16; warp tile 32 rows x 64 cols ----
    {
        wmma::fragment<wmma::accumulator, 16, 16, 8, float> acc[2][4];
#pragma unroll
        for (int i = 0; i < 2; i++)
#pragma unroll
            for (int j = 0; j < 4; j++) wmma::fill_fragment(acc[i][j], 0.f);

        for (int kc = 0; kc < 16; kc++) {           // 16-dim chunks of KD
            if (tid < 128) {
                int r = tid >> 2, c4 = (tid & 3) * 4;
                float4 f = *(const float4*)&q[base + (size_t)(m0 + r) * KD + kc * 16 + c4];
                *(float4*)&sQc[r * 20 + c4] = f;
            }
#pragma unroll
            for (int it = 0; it < 8; it++) {
                int lin = tid + it * 256;
                int r = lin >> 2, c4 = (lin & 3) * 4;
                float4 f = *(const float4*)&k[base + (size_t)r * KD + kc * 16 + c4];
                *(float4*)&sK[r * 20 + c4] = f;
            }
            __syncthreads();
#pragma unroll
            for (int kk = 0; kk < 2; kk++) {
                wmma::fragment<wmma::matrix_a, 16, 16, 8, wmma::precision::tf32, wmma::row_major> af[2];
#pragma unroll
                for (int i = 0; i < 2; i++)
                    wmma::load_matrix_sync(af[i], &sQc[(i * 16) * 20 + kk * 8], 20);
#pragma unroll
                for (int j = 0; j < 4; j++) {
                    wmma::fragment<wmma::matrix_b, 16, 16, 8, wmma::precision::tf32, wmma::col_major> bf;
                    wmma::load_matrix_sync(bf, &sK[(wid * 64 + j * 16) * 20 + kk * 8], 20);
#pragma unroll
                    for (int i = 0; i < 2; i++)
                        wmma::mma_sync(acc[i][j], af[i], bf, acc[i][j]);
                }
            }
            __syncthreads();
        }
#pragma unroll
        for (int i = 0; i < 2; i++)
#pragma unroll
            for (int j = 0; j < 4; j++) {
#pragma unroll
                for (int t = 0; t < acc[i][j].num_elements; t++) acc[i][j].x[t] *= 0.0625f;
                wmma::store_matrix_sync(&sS[(i * 16) * 516 + wid * 64 + j * 16],
                                        acc[i][j], 516, wmma::mem_row_major);
            }
    }
    __syncthreads();

    // ---- softmax: 8 warps x 4 rows ----
#pragma unroll
    for (int rr = 0; rr < 4; rr++) {
        int r = wid * 4 + rr;
        float mx = -1e30f;
        for (int c = lane; c < 512; c += 32) mx = fmaxf(mx, sS[r * 516 + c]);
#pragma unroll
        for (int o = 16; o; o >>= 1) mx = fmaxf(mx, __shfl_xor_sync(0xffffffffu, mx, o));
        float sum = 0.f;
        for (int c = lane; c < 512; c += 32) {
            float e = expf(sS[r * 516 + c] - mx);
            sS[r * 516 + c] = e;
            sum += e;
        }
#pragma unroll
        for (int o = 16; o; o >>= 1) sum += __shfl_xor_sync(0xffffffffu, sum, o);
        float inv = 1.f / sum;
        for (int c = lane; c < 512; c += 32) sS[r * 516 + c] *= inv;
    }
    __syncthreads();   // scores final; sK region free for per-warp V tiles

    // ---- phase 2: ctx = P @ V; warp tile 32 rows x 32 cols ----
    {
        float* sVw = sK + wid * (2 * 576);   // 2 buffers of 16x36

        wmma::fragment<wmma::accumulator, 16, 16, 8, float> acc2[2][2];
#pragma unroll
        for (int i = 0; i < 2; i++)
#pragma unroll
            for (int j = 0; j < 2; j++) wmma::fill_fragment(acc2[i][j], 0.f);

        auto stage_v = [&](int kc) {
            float* dst = sVw + (kc & 1) * 576;
#pragma unroll
            for (int it = 0; it < 4; it++) {
                int lin = lane + it * 32;
                int r = lin >> 3, c4 = (lin & 7) * 4;
                cpa16(&dst[r * 36 + c4],
                      &v[base + (size_t)(kc * 16 + r) * KD + wid * 32 + c4]);
            }
        };

        stage_v(0); CPA_COMMIT();

        for (int kc = 0; kc < 32; kc++) {
            if (kc + 1 < 32) { stage_v(kc + 1); CPA_COMMIT(); CPA_WAIT1(); }
            else             { CPA_WAIT0(); }
            __syncwarp();
            float* sVc = sVw + (kc & 1) * 576;
#pragma unroll
            for (int kk = 0; kk < 2; kk++) {
                wmma::fragment<wmma::matrix_a, 16, 16, 8, wmma::precision::tf32, wmma::row_major> af[2];
#pragma unroll
                for (int i = 0; i < 2; i++)
                    wmma::load_matrix_sync(af[i], &sS[(i * 16) * 516 + kc * 16 + kk * 8], 516);
#pragma unroll
                for (int j = 0; j < 2; j++) {
                    wmma::fragment<wmma::matrix_b, 16, 16, 8, wmma::precision::tf32, wmma::row_major> bf;
                    wmma::load_matrix_sync(bf, &sVc[(kk * 8) * 36 + j * 16], 36);
#pragma unroll
                    for (int i = 0; i < 2; i++)
                        wmma::mma_sync(acc2[i][j], af[i], bf, acc2[i][j]);
                }
            }
            __syncwarp();
        }

        const int b_ = bwh >> 4, w = (bwh >> 1) & 7, h = bwh & 1;
        const size_t tok0 = (size_t)b_ * SS + w * WINS + m0;
#pragma unroll
        for (int i = 0; i < 2; i++)
#pragma unroll
            for (int j = 0; j < 2; j++) {
                size_t row = tok0 + i * 16;
                int col = h * KD + wid * 32 + j * 16;
                wmma::store_matrix_sync(&ctx[row * (HH * KD) + col], acc2[i][j],
                                        HH * KD, wmma::mem_row_major);
            }
    }
}

// ---------------- launch ----------------------------------------------------
extern "C" void kernel_launch(void* const* d_in, const int* in_sizes, int n_in,
                              void* d_out, int out_size)
{
    const float* x    = (const float*)d_in[0];
    const float* Wq   = (const float*)d_in[1];
    const float* bq   = (const float*)d_in[2];
    const float* Wk   = (const float*)d_in[3];
    const float* bk   = (const float*)d_in[4];
    const float* Wv   = (const float*)d_in[5];
    const float* bv   = (const float*)d_in[6];
    const float* Wo   = (const float*)d_in[7];
    const float* bo   = (const float*)d_in[8];
    const float* ln1g = (const float*)d_in[9];
    const float* ln1b = (const float*)d_in[10];
    const float* W1   = (const float*)d_in[11];
    const float* b1   = (const float*)d_in[12];
    const float* W2   = (const float*)d_in[13];
    const float* b2   = (const float*)d_in[14];
    const float* ln2g = (const float*)d_in[15];
    const float* ln2b = (const float*)d_in[16];

    float *q, *k, *v, *ctx, *y, *hbuf;
    cudaGetSymbolAddress((void**)&q,    g_q);
    cudaGetSymbolAddress((void**)&k,    g_k);
    cudaGetSymbolAddress((void**)&v,    g_v);
    cudaGetSymbolAddress((void**)&ctx,  g_ctx);
    cudaGetSymbolAddress((void**)&y,    g_y);
    cudaGetSymbolAddress((void**)&hbuf, g_h);

    cudaFuncSetAttribute(attn_tc,    cudaFuncAttributeMaxDynamicSharedMemorySize, SMEM_ATTN);
    cudaFuncSetAttribute(qkv_tc,     cudaFuncAttributeMaxDynamicSharedMemorySize, GEMM_SMEM);
    cudaFuncSetAttribute(gemm_tc<1>, cudaFuncAttributeMaxDynamicSharedMemorySize, GEMM_SMEM);
    cudaFuncSetAttribute(gemm_tc<3>, cudaFuncAttributeMaxDynamicSharedMemorySize, GEMM_SMEM);

    dim3 blk(256);

    // fused QKV projections (scatter into [b,w,h,s,k]); N=512 -> 2 n-tiles
    qkv_tc<<<dim3(2, 256, 3), blk, GEMM_SMEM>>>(x, Wq, Wk, Wv, bq, bk, bv);

    // windowed attention
    attn_tc<<<dim3(16, 128), blk, SMEM_ATTN>>>(q, k, v, ctx);

    // output projection fused with residual+LN1: y = LN(ctx@Wo + bo + x)
    gemm_tc<3><<<dim3(1, 256), blk, GEMM_SMEM>>>(ctx, Wo, bo, y, DD, HH * KD,
                                                 x, ln1g, ln1b);

    // FFN: h = relu(y@W1 + b1)
    gemm_tc<1><<<dim3(4, 256), blk, GEMM_SMEM>>>(y, W1, b1, hbuf, DFF, DD,
                                                 nullptr, nullptr, nullptr);
    // out = LN(h@W2 + b2 + y)
    gemm_tc<3><<<dim3(1, 256), blk, GEMM_SMEM>>>(hbuf, W2, b2, (float*)d_out, DD, DFF,
                                                 y, ln2g, ln2b);
}